// round 7
// baseline (speedup 1.0000x reference)
#include <cuda_runtime.h>
#include <math.h>

// Problem dims
#define Vn 8000
#define Bn 64
#define Tn 256
#define Rn 1024
#define Un 512
#define Sn 1024
#define NROWS (Bn * Tn)  // 16384

// ---------------- device scratch (static globals; no runtime allocation) ----
__device__ float g_states[Tn * Bn * Rn];   // [t][b][r]  64 MB
__device__ float g_tmpA[Bn * Rn];
__device__ float g_tmpB[Bn * Rn];
__device__ float g_zero[Bn * Rn];
__device__ float g_outputs[NROWS * Un];    // 32 MB
__device__ float g_slog[NROWS * Sn];       // 64 MB
__device__ float g_tlog[NROWS];
__device__ float g_Ws[Sn * Un];            // gathered sampled softmax_w rows
__device__ float g_svec[Sn];               // softmax_b[sid] - log(sampled_counts)
__device__ int   g_sid[Sn];

// ---------------- helpers ---------------------------------------------------
__device__ __forceinline__ unsigned to_tf32(float x) {
    unsigned r;
    asm("cvt.rna.tf32.f32 %0, %1;" : "=r"(r) : "f"(x));
    return r;
}

__device__ __forceinline__ void mma8(float c[4],
                                     unsigned a0, unsigned a1, unsigned a2, unsigned a3,
                                     unsigned b0, unsigned b1) {
    asm volatile(
        "mma.sync.aligned.m16n8k8.row.col.f32.tf32.tf32.f32 "
        "{%0,%1,%2,%3},{%4,%5,%6,%7},{%8,%9},{%0,%1,%2,%3};"
        : "+f"(c[0]), "+f"(c[1]), "+f"(c[2]), "+f"(c[3])
        : "r"(a0), "r"(a1), "r"(a2), "r"(a3), "r"(b0), "r"(b1));
}

// ---------------- init: zero out, zero state0, gather sampled rows ----------
__global__ void __launch_bounds__(256) init_kernel(
    const int* __restrict__ sampled, const float* __restrict__ scnt,
    const float* __restrict__ sw, const float* __restrict__ sb,
    float* __restrict__ out)
{
    int gt = blockIdx.x * blockDim.x + threadIdx.x;
    int stride = gridDim.x * blockDim.x;
    if (gt == 0) out[0] = 0.0f;
    for (int i = gt; i < Bn * Rn; i += stride) g_zero[i] = 0.0f;
    for (int j = gt; j < Sn; j += stride) {
        int id = sampled[j];
        g_sid[j] = id;
        g_svec[j] = sb[id] - logf(scnt[j]);
    }
    for (int i = gt; i < Sn * Un; i += stride)
        g_Ws[i] = sw[(size_t)sampled[i >> 9] * Un + (i & 511)];
}

// ---------------- highway phase: dual GEMM (h,t) + gate epilogue ------------
// grid 32 CTAs, 256 threads. CTA c handles new-state cols [c*32, c*32+32).
// Warp tile: 16 rows x 16 cols for BOTH h and t (2 n8 tiles each).
__global__ void __launch_bounds__(256) highway_phase(
    const float* __restrict__ src, float* __restrict__ dst,
    const float* __restrict__ Wh, const float* __restrict__ Wt,
    const float* __restrict__ bh, const float* __restrict__ bt,
    const float* __restrict__ emb, const int* __restrict__ inp,
    int step, int K)
{
    __shared__ float catS[64][33];
    __shared__ float whS[32][33];
    __shared__ float wtS[32][33];

    const int tid = threadIdx.x;
    const int warp = tid >> 5, lane = tid & 31;
    const int g = lane >> 2, tig = lane & 3;
    const int rbase = (warp >> 1) * 16;
    const int cbase = (warp & 1) * 16;
    const int jbase = blockIdx.x * 32;

    float hc[2][4] = {{0.f,0.f,0.f,0.f},{0.f,0.f,0.f,0.f}};
    float tc[2][4] = {{0.f,0.f,0.f,0.f},{0.f,0.f,0.f,0.f}};

    for (int t0 = 0; t0 < K; t0 += 32) {
        // stage cat tile [64 rows(b)][32 k]
        #pragma unroll
        for (int r = 0; r < 2; r++) {
            int v = r * 256 + tid;      // 0..511
            int b = v >> 3, q = v & 7;
            int kg = t0 + q * 4;
            const float* p;
            if (emb != nullptr && kg < Un) {
                int tok = inp[b * Tn + step];
                p = emb + (size_t)tok * Un + kg;
            } else {
                int off = (emb != nullptr) ? (kg - Un) : kg;
                p = src + b * Rn + off;
            }
            float4 f = *(const float4*)p;
            catS[b][q*4+0] = __uint_as_float(to_tf32(f.x));
            catS[b][q*4+1] = __uint_as_float(to_tf32(f.y));
            catS[b][q*4+2] = __uint_as_float(to_tf32(f.z));
            catS[b][q*4+3] = __uint_as_float(to_tf32(f.w));
        }
        // stage weight tiles [32 k][32 j] — one float4 per thread per matrix
        {
            int kk = tid >> 3, q = tid & 7;
            float4 fh = *(const float4*)(Wh + (size_t)(t0 + kk) * Rn + jbase + q * 4);
            whS[kk][q*4+0] = __uint_as_float(to_tf32(fh.x));
            whS[kk][q*4+1] = __uint_as_float(to_tf32(fh.y));
            whS[kk][q*4+2] = __uint_as_float(to_tf32(fh.z));
            whS[kk][q*4+3] = __uint_as_float(to_tf32(fh.w));
            float4 ft = *(const float4*)(Wt + (size_t)(t0 + kk) * Rn + jbase + q * 4);
            wtS[kk][q*4+0] = __uint_as_float(to_tf32(ft.x));
            wtS[kk][q*4+1] = __uint_as_float(to_tf32(ft.y));
            wtS[kk][q*4+2] = __uint_as_float(to_tf32(ft.z));
            wtS[kk][q*4+3] = __uint_as_float(to_tf32(ft.w));
        }
        __syncthreads();

        #pragma unroll
        for (int k8 = 0; k8 < 32; k8 += 8) {
            unsigned a0 = __float_as_uint(catS[rbase + g    ][k8 + tig    ]);
            unsigned a1 = __float_as_uint(catS[rbase + g + 8][k8 + tig    ]);
            unsigned a2 = __float_as_uint(catS[rbase + g    ][k8 + tig + 4]);
            unsigned a3 = __float_as_uint(catS[rbase + g + 8][k8 + tig + 4]);
            #pragma unroll
            for (int nt = 0; nt < 2; nt++) {
                int j = cbase + nt * 8 + g;
                unsigned hb0 = __float_as_uint(whS[k8 + tig    ][j]);
                unsigned hb1 = __float_as_uint(whS[k8 + tig + 4][j]);
                mma8(hc[nt], a0, a1, a2, a3, hb0, hb1);
                unsigned tb0 = __float_as_uint(wtS[k8 + tig    ][j]);
                unsigned tb1 = __float_as_uint(wtS[k8 + tig + 4][j]);
                mma8(tc[nt], a0, a1, a2, a3, tb0, tb1);
            }
        }
        __syncthreads();
    }

    // highway epilogue: new = (tanh(h) - s) * sigmoid(t) + s
    #pragma unroll
    for (int nt = 0; nt < 2; nt++) {
        #pragma unroll
        for (int i = 0; i < 4; i++) {
            int b = rbase + g + ((i >= 2) ? 8 : 0);
            int j = jbase + cbase + nt * 8 + tig * 2 + (i & 1);
            float hl = hc[nt][i] + bh[j];
            float tl = tc[nt][i] + bt[j];
            float s  = src[b * Rn + j];
            float tg = 1.0f / (1.0f + __expf(-tl));
            float hv = tanhf(hl);
            dst[b * Rn + j] = (hv - s) * tg + s;
        }
    }
}

// ---------------- projection: outputs[m][u] = states . Wp + bp --------------
// grid (256, 8): CTA tile 64(m) x 64(n), K = 1024. Warp tile 16x32 (4 n8).
__global__ void __launch_bounds__(256) proj_kernel(
    const float* __restrict__ Wp, const float* __restrict__ bp)
{
    __shared__ float AS[64][33];
    __shared__ float BS[32][65];

    const int tid = threadIdx.x;
    const int warp = tid >> 5, lane = tid & 31;
    const int g = lane >> 2, tig = lane & 3;
    const int rbase = (warp >> 1) * 16;
    const int cbase = (warp & 1) * 32;
    const int m0 = blockIdx.x * 64, jb = blockIdx.y * 64;

    float c[4][4] = {{0}};
    #pragma unroll
    for (int nt = 0; nt < 4; nt++)
        #pragma unroll
        for (int i = 0; i < 4; i++) c[nt][i] = 0.f;

    for (int t0 = 0; t0 < Rn; t0 += 32) {
        #pragma unroll
        for (int r = 0; r < 2; r++) {
            int v = r * 256 + tid;          // 0..511
            int row = v >> 3, q = v & 7;
            int m = m0 + row;               // m = b*T + t
            const float* p = g_states + (size_t)(m & (Tn - 1)) * (Bn * Rn)
                                      + (size_t)(m >> 8) * Rn + t0 + q * 4;
            float4 f = *(const float4*)p;
            AS[row][q*4+0] = __uint_as_float(to_tf32(f.x));
            AS[row][q*4+1] = __uint_as_float(to_tf32(f.y));
            AS[row][q*4+2] = __uint_as_float(to_tf32(f.z));
            AS[row][q*4+3] = __uint_as_float(to_tf32(f.w));
        }
        #pragma unroll
        for (int r = 0; r < 2; r++) {
            int v = r * 256 + tid;          // 0..511 float4s
            int kk = v >> 4, jq = v & 15;
            float4 f = *(const float4*)(Wp + (size_t)(t0 + kk) * Un + jb + jq * 4);
            BS[kk][jq*4+0] = __uint_as_float(to_tf32(f.x));
            BS[kk][jq*4+1] = __uint_as_float(to_tf32(f.y));
            BS[kk][jq*4+2] = __uint_as_float(to_tf32(f.z));
            BS[kk][jq*4+3] = __uint_as_float(to_tf32(f.w));
        }
        __syncthreads();

        #pragma unroll
        for (int k8 = 0; k8 < 32; k8 += 8) {
            unsigned a0 = __float_as_uint(AS[rbase + g    ][k8 + tig    ]);
            unsigned a1 = __float_as_uint(AS[rbase + g + 8][k8 + tig    ]);
            unsigned a2 = __float_as_uint(AS[rbase + g    ][k8 + tig + 4]);
            unsigned a3 = __float_as_uint(AS[rbase + g + 8][k8 + tig + 4]);
            #pragma unroll
            for (int nt = 0; nt < 4; nt++) {
                int j = cbase + nt * 8 + g;
                unsigned b0 = __float_as_uint(BS[k8 + tig    ][j]);
                unsigned b1 = __float_as_uint(BS[k8 + tig + 4][j]);
                mma8(c[nt], a0, a1, a2, a3, b0, b1);
            }
        }
        __syncthreads();
    }

    #pragma unroll
    for (int nt = 0; nt < 4; nt++) {
        #pragma unroll
        for (int i = 0; i < 4; i++) {
            int m = m0 + rbase + g + ((i >= 2) ? 8 : 0);
            int j = jb + cbase + nt * 8 + tig * 2 + (i & 1);
            g_outputs[(size_t)m * Un + j] = c[nt][i] + bp[j];
        }
    }
}

// ---------------- sampled logits: outputs @ Ws^T + svec, hit mask ----------
// grid (256, 16): CTA tile 64(m) x 64(n), K = 512.
__global__ void __launch_bounds__(256) slog_kernel(const int* __restrict__ labels)
{
    __shared__ float AS[64][33];
    __shared__ float BS[32][65];

    const int tid = threadIdx.x;
    const int warp = tid >> 5, lane = tid & 31;
    const int g = lane >> 2, tig = lane & 3;
    const int rbase = (warp >> 1) * 16;
    const int cbase = (warp & 1) * 32;
    const int m0 = blockIdx.x * 64, jb = blockIdx.y * 64;

    float c[4][4];
    #pragma unroll
    for (int nt = 0; nt < 4; nt++)
        #pragma unroll
        for (int i = 0; i < 4; i++) c[nt][i] = 0.f;

    for (int t0 = 0; t0 < Un; t0 += 32) {
        #pragma unroll
        for (int r = 0; r < 2; r++) {
            int v = r * 256 + tid;
            int row = v >> 3, q = v & 7;
            const float* p = g_outputs + (size_t)(m0 + row) * Un + t0 + q * 4;
            float4 f = *(const float4*)p;
            AS[row][q*4+0] = __uint_as_float(to_tf32(f.x));
            AS[row][q*4+1] = __uint_as_float(to_tf32(f.y));
            AS[row][q*4+2] = __uint_as_float(to_tf32(f.z));
            AS[row][q*4+3] = __uint_as_float(to_tf32(f.w));
        }
        // B = Ws[j][k] (row-major n x k == col-major k x n): transpose into BS[k][j]
        #pragma unroll
        for (int r = 0; r < 2; r++) {
            int v = r * 256 + tid;          // 0..511
            int j = v >> 3, q = v & 7;
            float4 f = *(const float4*)(g_Ws + (size_t)(jb + j) * Un + t0 + q * 4);
            BS[q*4+0][j] = __uint_as_float(to_tf32(f.x));
            BS[q*4+1][j] = __uint_as_float(to_tf32(f.y));
            BS[q*4+2][j] = __uint_as_float(to_tf32(f.z));
            BS[q*4+3][j] = __uint_as_float(to_tf32(f.w));
        }
        __syncthreads();

        #pragma unroll
        for (int k8 = 0; k8 < 32; k8 += 8) {
            unsigned a0 = __float_as_uint(AS[rbase + g    ][k8 + tig    ]);
            unsigned a1 = __float_as_uint(AS[rbase + g + 8][k8 + tig    ]);
            unsigned a2 = __float_as_uint(AS[rbase + g    ][k8 + tig + 4]);
            unsigned a3 = __float_as_uint(AS[rbase + g + 8][k8 + tig + 4]);
            #pragma unroll
            for (int nt = 0; nt < 4; nt++) {
                int j = cbase + nt * 8 + g;
                unsigned b0 = __float_as_uint(BS[k8 + tig    ][j]);
                unsigned b1 = __float_as_uint(BS[k8 + tig + 4][j]);
                mma8(c[nt], a0, a1, a2, a3, b0, b1);
            }
        }
        __syncthreads();
    }

    #pragma unroll
    for (int nt = 0; nt < 4; nt++) {
        #pragma unroll
        for (int i = 0; i < 4; i++) {
            int m = m0 + rbase + g + ((i >= 2) ? 8 : 0);
            int j = jb + cbase + nt * 8 + tig * 2 + (i & 1);
            float v = c[nt][i] + g_svec[j];
            if (labels[m] == g_sid[j]) v -= 1e9f;
            g_slog[(size_t)m * Sn + j] = v;
        }
    }
}

// ---------------- true logits: warp per row ---------------------------------
__global__ void __launch_bounds__(256) tlog_kernel(
    const int* __restrict__ labels, const float* __restrict__ sw,
    const float* __restrict__ sb, const float* __restrict__ tcnt)
{
    int warp = threadIdx.x >> 5, lane = threadIdx.x & 31;
    int n = blockIdx.x * 8 + warp;
    int lab = labels[n];
    const float4* o = (const float4*)(g_outputs + (size_t)n * Un);
    const float4* w = (const float4*)(sw + (size_t)lab * Un);
    float acc = 0.f;
    #pragma unroll
    for (int q = 0; q < 4; q++) {
        float4 a = o[lane + q * 32];
        float4 b = w[lane + q * 32];
        acc += a.x * b.x + a.y * b.y + a.z * b.z + a.w * b.w;
    }
    #pragma unroll
    for (int s = 16; s; s >>= 1) acc += __shfl_xor_sync(0xffffffffu, acc, s);
    if (lane == 0) g_tlog[n] = acc + sb[lab] - logf(tcnt[n]);
}

// ---------------- loss: warp per row, online logsumexp ----------------------
__global__ void __launch_bounds__(256) loss_kernel(float* __restrict__ out)
{
    __shared__ float red[8];
    int warp = threadIdx.x >> 5, lane = threadIdx.x & 31;
    int n = blockIdx.x * 8 + warp;

    float mL = -INFINITY, sL = 0.f;
    const float* row = g_slog + (size_t)n * Sn;
    for (int j = lane; j < Sn; j += 32) {
        float v = row[j];
        if (v > mL) { sL = sL * __expf(mL - v) + 1.f; mL = v; }
        else          sL += __expf(v - mL);
    }
    #pragma unroll
    for (int s = 16; s; s >>= 1) {
        float m2 = __shfl_xor_sync(0xffffffffu, mL, s);
        float s2 = __shfl_xor_sync(0xffffffffu, sL, s);
        float M = fmaxf(mL, m2);
        sL = sL * __expf(mL - M) + s2 * __expf(m2 - M);
        mL = M;
    }
    float z0 = g_tlog[n];
    float M = fmaxf(mL, z0);
    float S = sL * __expf(mL - M) + __expf(z0 - M);
    float loss = (M + logf(S)) - z0;

    if (lane == 0) red[warp] = loss;
    __syncthreads();
    if (threadIdx.x == 0) {
        float t = 0.f;
        #pragma unroll
        for (int i = 0; i < 8; i++) t += red[i];
        atomicAdd(out, t * (1.0f / NROWS));
    }
}

// ---------------- launch ----------------------------------------------------
extern "C" void kernel_launch(void* const* d_in, const int* in_sizes, int n_in,
                              void* d_out, int out_size)
{
    (void)in_sizes; (void)n_in; (void)out_size;

    const int*   input   = (const int*)  d_in[0];
    const int*   targets = (const int*)  d_in[1];
    const int*   sampled = (const int*)  d_in[2];
    const float* tcnt    = (const float*)d_in[3];
    const float* scnt    = (const float*)d_in[4];
    const float* emb     = (const float*)d_in[5];
    const float* Wh0     = (const float*)d_in[6];
    const float* bh0     = (const float*)d_in[7];
    const float* Wt0     = (const float*)d_in[8];
    const float* bt0     = (const float*)d_in[9];
    const float* Wh      = (const float*)d_in[10];
    const float* bh      = (const float*)d_in[11];
    const float* Wt      = (const float*)d_in[12];
    const float* bt      = (const float*)d_in[13];
    const float* Wp      = (const float*)d_in[14];
    const float* bp      = (const float*)d_in[15];
    const float* sw      = (const float*)d_in[16];
    const float* sb      = (const float*)d_in[17];
    float* out = (float*)d_out;

    float *states, *tmpA, *tmpB, *zero;
    cudaGetSymbolAddress((void**)&states, g_states);
    cudaGetSymbolAddress((void**)&tmpA,   g_tmpA);
    cudaGetSymbolAddress((void**)&tmpB,   g_tmpB);
    cudaGetSymbolAddress((void**)&zero,   g_zero);

    init_kernel<<<256, 256>>>(sampled, scnt, sw, sb, out);

    for (int step = 0; step < Tn; step++) {
        const float* src0 = (step == 0) ? zero : (states + (size_t)(step - 1) * Bn * Rn);
        highway_phase<<<32, 256>>>(src0, tmpA, Wh0, Wt0, bh0, bt0,
                                   emb, input, step, Un + Rn);
        highway_phase<<<32, 256>>>(tmpA, tmpB, Wh, Wt, bh, bt,
                                   nullptr, nullptr, 0, Rn);
        highway_phase<<<32, 256>>>(tmpB, states + (size_t)step * Bn * Rn,
                                   Wh + (size_t)Rn * Rn, Wt + (size_t)Rn * Rn,
                                   bh + Rn, bt + Rn,
                                   nullptr, nullptr, 0, Rn);
    }

    proj_kernel<<<dim3(NROWS / 64, Un / 64), 256>>>(Wp, bp);
    slog_kernel<<<dim3(NROWS / 64, Sn / 64), 256>>>(targets);
    tlog_kernel<<<NROWS / 8, 256>>>(targets, sw, sb, tcnt);
    loss_kernel<<<NROWS / 8, 256>>>(out);
}

// round 9
// speedup vs baseline: 3.3256x; 3.3256x over previous
#include <cuda_runtime.h>
#include <cuda_bf16.h>
#include <math.h>

// Problem dims
#define Vn 8000
#define Bn 64
#define Tn 256
#define Rn 1024
#define Un 512
#define Sn 1024
#define NROWS (Bn * Tn)  // 16384

#define NCTA 128
#define ABUF_EL (64 * 136)   // one A chunk buffer: 64 rows x 128 cols (pad 136)

// ---------------- device scratch (static globals; no runtime allocation) ----
__device__ float g_states[Tn * Bn * Rn];   // [t][b][r] fp32 final states
__device__ float g_tmpA[Bn * Rn];
__device__ float g_tmpB[Bn * Rn];
__device__ float g_zero[Bn * Rn];
__device__ float g_outputs[NROWS * Un];
__device__ float g_slog[NROWS * Sn];
__device__ float g_tlog[NROWS];
__device__ float g_Ws[Sn * Un];
__device__ float g_svec[Sn];
__device__ int   g_sid[Sn];

// bf16 scan data
__device__ __nv_bfloat16 g_xb[NROWS * Un];                    // [t][b][u]
__device__ __nv_bfloat16 g_WbH[1024 * 1536 + 2 * 1024 * 1024]; // [j][k] x3 layers
__device__ __nv_bfloat16 g_WbT[1024 * 1536 + 2 * 1024 * 1024];
__device__ __nv_bfloat16 g_sB[2 * Bn * Rn];                   // ping-pong bf16 state
__device__ __nv_bfloat16 g_tmpA_B[Bn * Rn];
__device__ __nv_bfloat16 g_tmpB_B[Bn * Rn];

// grid barrier state
__device__ unsigned g_barCount;
__device__ unsigned g_barGen;

// ---------------- helpers ---------------------------------------------------
__device__ __forceinline__ unsigned to_tf32(float x) {
    unsigned r;
    asm("cvt.rna.tf32.f32 %0, %1;" : "=r"(r) : "f"(x));
    return r;
}

__device__ __forceinline__ void mma8(float c[4],
                                     unsigned a0, unsigned a1, unsigned a2, unsigned a3,
                                     unsigned b0, unsigned b1) {
    asm volatile(
        "mma.sync.aligned.m16n8k8.row.col.f32.tf32.tf32.f32 "
        "{%0,%1,%2,%3},{%4,%5,%6,%7},{%8,%9},{%0,%1,%2,%3};"
        : "+f"(c[0]), "+f"(c[1]), "+f"(c[2]), "+f"(c[3])
        : "r"(a0), "r"(a1), "r"(a2), "r"(a3), "r"(b0), "r"(b1));
}

__device__ __forceinline__ void mma_bf16(float c[4],
                                         unsigned a0, unsigned a1, unsigned a2, unsigned a3,
                                         unsigned b0, unsigned b1) {
    asm volatile(
        "mma.sync.aligned.m16n8k16.row.col.f32.bf16.bf16.f32 "
        "{%0,%1,%2,%3},{%4,%5,%6,%7},{%8,%9},{%0,%1,%2,%3};"
        : "+f"(c[0]), "+f"(c[1]), "+f"(c[2]), "+f"(c[3])
        : "r"(a0), "r"(a1), "r"(a2), "r"(a3), "r"(b0), "r"(b1));
}

__device__ __forceinline__ void cpa16(void* dst, const void* src) {
    unsigned d = (unsigned)__cvta_generic_to_shared(dst);
    asm volatile("cp.async.cg.shared.global [%0], [%1], 16;" :: "r"(d), "l"(src));
}

// ---------------- init ------------------------------------------------------
__global__ void __launch_bounds__(256) init_kernel(
    const int* __restrict__ sampled, const float* __restrict__ scnt,
    const float* __restrict__ sw, const float* __restrict__ sb,
    float* __restrict__ out)
{
    int gt = blockIdx.x * blockDim.x + threadIdx.x;
    int stride = gridDim.x * blockDim.x;
    if (gt == 0) { out[0] = 0.0f; g_barCount = 0u; g_barGen = 0u; }
    unsigned* sb32 = (unsigned*)g_sB;   // 2*Bn*Rn bf16 == Bn*Rn words
    for (int i = gt; i < Bn * Rn; i += stride) { g_zero[i] = 0.0f; sb32[i] = 0u; }
    for (int j = gt; j < Sn; j += stride) {
        int id = sampled[j];
        g_sid[j] = id;
        g_svec[j] = sb[id] - logf(scnt[j]);
    }
    for (int i = gt; i < Sn * Un; i += stride)
        g_Ws[i] = sw[(size_t)sampled[i >> 9] * Un + (i & 511)];
}

// ---------------- weight transpose/convert: f32 [K][1024] -> bf16 [1024][K] -
__global__ void __launch_bounds__(256) wconv_kernel(
    const float* __restrict__ src, int which, size_t dstOff, int K)
{
    __shared__ float tile[32][33];
    __nv_bfloat16* dst = (which ? g_WbT : g_WbH) + dstOff;
    int k0 = blockIdx.x * 32, j0 = blockIdx.y * 32;
    int tx = threadIdx.x & 31, ty = threadIdx.x >> 5;   // ty 0..7
    for (int r = ty; r < 32; r += 8)
        tile[r][tx] = src[(size_t)(k0 + r) * 1024 + j0 + tx];
    __syncthreads();
    for (int r = ty; r < 32; r += 8)
        dst[(size_t)(j0 + r) * K + k0 + tx] = __float2bfloat16_rn(tile[tx][r]);
}

// ---------------- emb pre-gather: g_xb[t*64+b][u] = bf16(emb[tok][u]) -------
__global__ void __launch_bounds__(128) xconv_kernel(
    const int* __restrict__ inp, const float* __restrict__ emb)
{
    int idx = blockIdx.x;               // t*64 + b
    int b = idx & 63, t = idx >> 6;
    int tok = inp[b * Tn + t];
    const float4* s = (const float4*)(emb + (size_t)tok * Un);
    __nv_bfloat162* d2 = (__nv_bfloat162*)(g_xb + (size_t)idx * Un);
    int v = threadIdx.x;                // 128 threads x 1 float4 = 512 elems
    float4 f = s[v];
    __nv_bfloat162 p0, p1;
    p0.x = __float2bfloat16_rn(f.x); p0.y = __float2bfloat16_rn(f.y);
    p1.x = __float2bfloat16_rn(f.z); p1.y = __float2bfloat16_rn(f.w);
    d2[2 * v] = p0;
    d2[2 * v + 1] = p1;
}

// ---------------- persistent scan kernel ------------------------------------
__device__ __forceinline__ void loadChunk(__nv_bfloat16* dst,
    const __nv_bfloat16* aEmb, const __nv_bfloat16* aState, int k0, int tid)
{
    #pragma unroll
    for (int r = 0; r < 4; r++) {
        int ln = tid + r * 256;          // 1024 lines of 16B
        int row = ln >> 4, seg = ln & 15;
        int k = k0 + seg * 8;
        const __nv_bfloat16* src;
        if (aEmb != nullptr && k < Un) {
            src = aEmb + row * Un + k;
        } else {
            int kk = (aEmb != nullptr) ? (k - Un) : k;
            src = aState + row * Rn + kk;
        }
        cpa16(dst + row * 136 + seg * 8, src);
    }
}

__device__ void doPhase(
    int K,
    const __nv_bfloat16* __restrict__ WH, const __nv_bfloat16* __restrict__ WT,
    const __nv_bfloat16* __restrict__ aEmb,    // nullable: first 512 cols
    const __nv_bfloat16* __restrict__ aState,  // remaining cols
    const float* __restrict__ sF,
    const float* __restrict__ bhp, const float* __restrict__ btp,
    float* __restrict__ dstF, __nv_bfloat16* __restrict__ dstB,
    __nv_bfloat16* abuf, float* hraw, float* traw,
    int jbase, int tid, int w, int lane)
{
    const int g = lane >> 2, tig = lane & 3;
    const int mat = w >> 2;
    const int rbase = (w & 3) * 16;
    const int NCH = K >> 7;

    float acc0[4] = {0.f, 0.f, 0.f, 0.f}, acc1[4] = {0.f, 0.f, 0.f, 0.f};
    const unsigned* bw = (const unsigned*)((mat ? WT : WH) + (size_t)(jbase + g) * K);

    loadChunk(abuf, aEmb, aState, 0, tid);
    asm volatile("cp.async.commit_group;");

    for (int c = 0; c < NCH; c++) {
        __syncthreads();   // buf (c+1)&1 free (chunk c-1 compute done)
        if (c + 1 < NCH) {
            loadChunk(abuf + ((c + 1) & 1) * ABUF_EL, aEmb, aState, (c + 1) << 7, tid);
            asm volatile("cp.async.commit_group;");
            asm volatile("cp.async.wait_group 1;");
        } else {
            asm volatile("cp.async.wait_group 0;");
        }
        __syncthreads();   // chunk c visible to all
        const unsigned* ar = (const unsigned*)(abuf + (c & 1) * ABUF_EL)
                             + (rbase + g) * 68 + tig;
        const unsigned* br = bw + c * 64 + tig;
        #pragma unroll
        for (int s = 0; s < 8; s++) {
            unsigned a0 = ar[s * 8],     a1 = ar[s * 8 + 544];
            unsigned a2 = ar[s * 8 + 4], a3 = ar[s * 8 + 548];
            unsigned b0 = __ldg(br + s * 8), b1 = __ldg(br + s * 8 + 4);
            if (s & 1) mma_bf16(acc1, a0, a1, a2, a3, b0, b1);
            else       mma_bf16(acc0, a0, a1, a2, a3, b0, b1);
        }
    }
    float* raw = mat ? traw : hraw;
    int r0 = rbase + g;
    raw[r0 * 9 + 2 * tig]           = acc0[0] + acc1[0];
    raw[r0 * 9 + 2 * tig + 1]       = acc0[1] + acc1[1];
    raw[(r0 + 8) * 9 + 2 * tig]     = acc0[2] + acc1[2];
    raw[(r0 + 8) * 9 + 2 * tig + 1] = acc0[3] + acc1[3];
    __syncthreads();
    #pragma unroll
    for (int r = 0; r < 2; r++) {
        int v = tid + r * 256;
        int b = v >> 3, jj = v & 7, j = jbase + jj;
        float hpre = hraw[b * 9 + jj] + __ldg(&bhp[j]);
        float tpre = traw[b * 9 + jj] + __ldg(&btp[j]);
        float s = __ldcg(&sF[b * Rn + j]);
        float tg = 1.0f / (1.0f + __expf(-tpre));
        float o = (tanhf(hpre) - s) * tg + s;
        dstF[b * Rn + j] = o;
        dstB[b * Rn + j] = __float2bfloat16_rn(o);
    }
}

__device__ __forceinline__ void gridBarrier(unsigned want) {
    __threadfence();
    __syncthreads();
    if (threadIdx.x == 0) {
        unsigned t = atomicAdd(&g_barCount, 1u);
        if (t == NCTA - 1) {
            g_barCount = 0u;
            __threadfence();
            atomicExch(&g_barGen, want);
        } else {
            while (*((volatile unsigned*)&g_barGen) < want) __nanosleep(64);
        }
        __threadfence();
    }
    __syncthreads();
}

__global__ void __launch_bounds__(256) scan_kernel(
    const float* __restrict__ bh0, const float* __restrict__ bt0,
    const float* __restrict__ bh, const float* __restrict__ bt)
{
    __shared__ __nv_bfloat16 abuf[2 * ABUF_EL];   // 34816 B
    __shared__ float hraw[64 * 9];
    __shared__ float traw[64 * 9];

    const int tid = threadIdx.x, w = tid >> 5, lane = tid & 31;
    const int jbase = blockIdx.x * 8;
    const size_t OFF1 = (size_t)1024 * 1536;
    const size_t OFF2 = OFF1 + (size_t)1024 * 1024;

    unsigned want = 0;
    for (int t = 0; t < Tn; t++) {
        const __nv_bfloat16* xbt    = g_xb + (size_t)t * Bn * Un;
        const __nv_bfloat16* sBprev = g_sB + (size_t)((t + 1) & 1) * Bn * Rn;
        const float* sFprev = (t == 0) ? g_zero : (g_states + (size_t)(t - 1) * Bn * Rn);

        doPhase(1536, g_WbH, g_WbT, xbt, sBprev, sFprev, bh0, bt0,
                g_tmpA, g_tmpA_B, abuf, hraw, traw, jbase, tid, w, lane);
        gridBarrier(++want);
        doPhase(1024, g_WbH + OFF1, g_WbT + OFF1, nullptr, g_tmpA_B, g_tmpA,
                bh, bt, g_tmpB, g_tmpB_B, abuf, hraw, traw, jbase, tid, w, lane);
        gridBarrier(++want);
        doPhase(1024, g_WbH + OFF2, g_WbT + OFF2, nullptr, g_tmpB_B, g_tmpB,
                bh + Rn, bt + Rn,
                g_states + (size_t)t * Bn * Rn, g_sB + (size_t)(t & 1) * Bn * Rn,
                abuf, hraw, traw, jbase, tid, w, lane);
        gridBarrier(++want);
    }
}

// ---------------- projection: outputs[m][u] = states . Wp + bp --------------
__global__ void __launch_bounds__(256) proj_kernel(
    const float* __restrict__ Wp, const float* __restrict__ bp)
{
    __shared__ float AS[64][33];
    __shared__ float BS[32][65];

    const int tid = threadIdx.x;
    const int warp = tid >> 5, lane = tid & 31;
    const int g = lane >> 2, tig = lane & 3;
    const int rbase = (warp >> 1) * 16;
    const int cbase = (warp & 1) * 32;
    const int m0 = blockIdx.x * 64, jb = blockIdx.y * 64;

    float c[4][4];
    #pragma unroll
    for (int nt = 0; nt < 4; nt++)
        #pragma unroll
        for (int i = 0; i < 4; i++) c[nt][i] = 0.f;

    for (int t0 = 0; t0 < Rn; t0 += 32) {
        #pragma unroll
        for (int r = 0; r < 2; r++) {
            int v = r * 256 + tid;
            int row = v >> 3, q = v & 7;
            int m = m0 + row;
            const float* p = g_states + (size_t)(m & (Tn - 1)) * (Bn * Rn)
                                      + (size_t)(m >> 8) * Rn + t0 + q * 4;
            float4 f = *(const float4*)p;
            AS[row][q*4+0] = __uint_as_float(to_tf32(f.x));
            AS[row][q*4+1] = __uint_as_float(to_tf32(f.y));
            AS[row][q*4+2] = __uint_as_float(to_tf32(f.z));
            AS[row][q*4+3] = __uint_as_float(to_tf32(f.w));
        }
        #pragma unroll
        for (int r = 0; r < 2; r++) {
            int v = r * 256 + tid;
            int kk = v >> 4, jq = v & 15;
            float4 f = *(const float4*)(Wp + (size_t)(t0 + kk) * Un + jb + jq * 4);
            BS[kk][jq*4+0] = __uint_as_float(to_tf32(f.x));
            BS[kk][jq*4+1] = __uint_as_float(to_tf32(f.y));
            BS[kk][jq*4+2] = __uint_as_float(to_tf32(f.z));
            BS[kk][jq*4+3] = __uint_as_float(to_tf32(f.w));
        }
        __syncthreads();

        #pragma unroll
        for (int k8 = 0; k8 < 32; k8 += 8) {
            unsigned a0 = __float_as_uint(AS[rbase + g    ][k8 + tig    ]);
            unsigned a1 = __float_as_uint(AS[rbase + g + 8][k8 + tig    ]);
            unsigned a2 = __float_as_uint(AS[rbase + g    ][k8 + tig + 4]);
            unsigned a3 = __float_as_uint(AS[rbase + g + 8][k8 + tig + 4]);
            #pragma unroll
            for (int nt = 0; nt < 4; nt++) {
                int j = cbase + nt * 8 + g;
                unsigned b0 = __float_as_uint(BS[k8 + tig    ][j]);
                unsigned b1 = __float_as_uint(BS[k8 + tig + 4][j]);
                mma8(c[nt], a0, a1, a2, a3, b0, b1);
            }
        }
        __syncthreads();
    }

    #pragma unroll
    for (int nt = 0; nt < 4; nt++) {
        #pragma unroll
        for (int i = 0; i < 4; i++) {
            int m = m0 + rbase + g + ((i >= 2) ? 8 : 0);
            int j = jb + cbase + nt * 8 + tig * 2 + (i & 1);
            g_outputs[(size_t)m * Un + j] = c[nt][i] + bp[j];
        }
    }
}

// ---------------- sampled logits: outputs @ Ws^T + svec, hit mask -----------
__global__ void __launch_bounds__(256) slog_kernel(const int* __restrict__ labels)
{
    __shared__ float AS[64][33];
    __shared__ float BS[32][65];

    const int tid = threadIdx.x;
    const int warp = tid >> 5, lane = tid & 31;
    const int g = lane >> 2, tig = lane & 3;
    const int rbase = (warp >> 1) * 16;
    const int cbase = (warp & 1) * 32;
    const int m0 = blockIdx.x * 64, jb = blockIdx.y * 64;

    float c[4][4];
    #pragma unroll
    for (int nt = 0; nt < 4; nt++)
        #pragma unroll
        for (int i = 0; i < 4; i++) c[nt][i] = 0.f;

    for (int t0 = 0; t0 < Un; t0 += 32) {
        #pragma unroll
        for (int r = 0; r < 2; r++) {
            int v = r * 256 + tid;
            int row = v >> 3, q = v & 7;
            const float* p = g_outputs + (size_t)(m0 + row) * Un + t0 + q * 4;
            float4 f = *(const float4*)p;
            AS[row][q*4+0] = __uint_as_float(to_tf32(f.x));
            AS[row][q*4+1] = __uint_as_float(to_tf32(f.y));
            AS[row][q*4+2] = __uint_as_float(to_tf32(f.z));
            AS[row][q*4+3] = __uint_as_float(to_tf32(f.w));
        }
        #pragma unroll
        for (int r = 0; r < 2; r++) {
            int v = r * 256 + tid;
            int j = v >> 3, q = v & 7;
            float4 f = *(const float4*)(g_Ws + (size_t)(jb + j) * Un + t0 + q * 4);
            BS[q*4+0][j] = __uint_as_float(to_tf32(f.x));
            BS[q*4+1][j] = __uint_as_float(to_tf32(f.y));
            BS[q*4+2][j] = __uint_as_float(to_tf32(f.z));
            BS[q*4+3][j] = __uint_as_float(to_tf32(f.w));
        }
        __syncthreads();

        #pragma unroll
        for (int k8 = 0; k8 < 32; k8 += 8) {
            unsigned a0 = __float_as_uint(AS[rbase + g    ][k8 + tig    ]);
            unsigned a1 = __float_as_uint(AS[rbase + g + 8][k8 + tig    ]);
            unsigned a2 = __float_as_uint(AS[rbase + g    ][k8 + tig + 4]);
            unsigned a3 = __float_as_uint(AS[rbase + g + 8][k8 + tig + 4]);
            #pragma unroll
            for (int nt = 0; nt < 4; nt++) {
                int j = cbase + nt * 8 + g;
                unsigned b0 = __float_as_uint(BS[k8 + tig    ][j]);
                unsigned b1 = __float_as_uint(BS[k8 + tig + 4][j]);
                mma8(c[nt], a0, a1, a2, a3, b0, b1);
            }
        }
        __syncthreads();
    }

    #pragma unroll
    for (int nt = 0; nt < 4; nt++) {
        #pragma unroll
        for (int i = 0; i < 4; i++) {
            int m = m0 + rbase + g + ((i >= 2) ? 8 : 0);
            int j = jb + cbase + nt * 8 + tig * 2 + (i & 1);
            float v = c[nt][i] + g_svec[j];
            if (labels[m] == g_sid[j]) v -= 1e9f;
            g_slog[(size_t)m * Sn + j] = v;
        }
    }
}

// ---------------- true logits: warp per row ---------------------------------
__global__ void __launch_bounds__(256) tlog_kernel(
    const int* __restrict__ labels, const float* __restrict__ sw,
    const float* __restrict__ sb, const float* __restrict__ tcnt)
{
    int warp = threadIdx.x >> 5, lane = threadIdx.x & 31;
    int n = blockIdx.x * 8 + warp;
    int lab = labels[n];
    const float4* o = (const float4*)(g_outputs + (size_t)n * Un);
    const float4* w = (const float4*)(sw + (size_t)lab * Un);
    float acc = 0.f;
    #pragma unroll
    for (int q = 0; q < 4; q++) {
        float4 a = o[lane + q * 32];
        float4 b = w[lane + q * 32];
        acc += a.x * b.x + a.y * b.y + a.z * b.z + a.w * b.w;
    }
    #pragma unroll
    for (int s = 16; s; s >>= 1) acc += __shfl_xor_sync(0xffffffffu, acc, s);
    if (lane == 0) g_tlog[n] = acc + sb[lab] - logf(tcnt[n]);
}

// ---------------- loss: warp per row, online logsumexp ----------------------
__global__ void __launch_bounds__(256) loss_kernel(float* __restrict__ out)
{
    __shared__ float red[8];
    int warp = threadIdx.x >> 5, lane = threadIdx.x & 31;
    int n = blockIdx.x * 8 + warp;

    float mL = -INFINITY, sL = 0.f;
    const float* row = g_slog + (size_t)n * Sn;
    for (int j = lane; j < Sn; j += 32) {
        float v = row[j];
        if (v > mL) { sL = sL * __expf(mL - v) + 1.f; mL = v; }
        else          sL += __expf(v - mL);
    }
    #pragma unroll
    for (int s = 16; s; s >>= 1) {
        float m2 = __shfl_xor_sync(0xffffffffu, mL, s);
        float s2 = __shfl_xor_sync(0xffffffffu, sL, s);
        float M = fmaxf(mL, m2);
        sL = sL * __expf(mL - M) + s2 * __expf(m2 - M);
        mL = M;
    }
    float z0 = g_tlog[n];
    float M = fmaxf(mL, z0);
    float S = sL * __expf(mL - M) + __expf(z0 - M);
    float loss = (M + logf(S)) - z0;

    if (lane == 0) red[warp] = loss;
    __syncthreads();
    if (threadIdx.x == 0) {
        float t = 0.f;
        #pragma unroll
        for (int i = 0; i < 8; i++) t += red[i];
        atomicAdd(out, t * (1.0f / NROWS));
    }
}

// ---------------- launch ----------------------------------------------------
extern "C" void kernel_launch(void* const* d_in, const int* in_sizes, int n_in,
                              void* d_out, int out_size)
{
    (void)in_sizes; (void)n_in; (void)out_size;

    const int*   input   = (const int*)  d_in[0];
    const int*   targets = (const int*)  d_in[1];
    const int*   sampled = (const int*)  d_in[2];
    const float* tcnt    = (const float*)d_in[3];
    const float* scnt    = (const float*)d_in[4];
    const float* emb     = (const float*)d_in[5];
    const float* Wh0     = (const float*)d_in[6];
    const float* bh0     = (const float*)d_in[7];
    const float* Wt0     = (const float*)d_in[8];
    const float* bt0     = (const float*)d_in[9];
    const float* Wh      = (const float*)d_in[10];
    const float* bh      = (const float*)d_in[11];
    const float* Wt      = (const float*)d_in[12];
    const float* bt      = (const float*)d_in[13];
    const float* Wp      = (const float*)d_in[14];
    const float* bp      = (const float*)d_in[15];
    const float* sw      = (const float*)d_in[16];
    const float* sb      = (const float*)d_in[17];
    float* out = (float*)d_out;

    const size_t OFF1 = (size_t)1024 * 1536;
    const size_t OFF2 = OFF1 + (size_t)1024 * 1024;

    init_kernel<<<256, 256>>>(sampled, scnt, sw, sb, out);

    // weight transpose/convert (once per run; inside graph for determinism)
    wconv_kernel<<<dim3(48, 32), 256>>>(Wh0, 0, 0, 1536);
    wconv_kernel<<<dim3(48, 32), 256>>>(Wt0, 1, 0, 1536);
    wconv_kernel<<<dim3(32, 32), 256>>>(Wh,                       0, OFF1, 1024);
    wconv_kernel<<<dim3(32, 32), 256>>>(Wt,                       1, OFF1, 1024);
    wconv_kernel<<<dim3(32, 32), 256>>>(Wh + (size_t)Rn * Rn,     0, OFF2, 1024);
    wconv_kernel<<<dim3(32, 32), 256>>>(Wt + (size_t)Rn * Rn,     1, OFF2, 1024);

    xconv_kernel<<<NROWS, 128>>>(input, emb);

    // the whole 256-step x 3-layer scan in ONE persistent kernel
    scan_kernel<<<NCTA, 256>>>(bh0, bt0, bh, bt);

    proj_kernel<<<dim3(NROWS / 64, Un / 64), 256>>>(Wp, bp);
    slog_kernel<<<dim3(NROWS / 64, Sn / 64), 256>>>(targets);
    tlog_kernel<<<NROWS / 8, 256>>>(targets, sw, sb, tcnt);
    loss_kernel<<<NROWS / 8, 256>>>(out);
}

// round 10
// speedup vs baseline: 4.2824x; 1.2877x over previous
#include <cuda_runtime.h>
#include <cuda_bf16.h>
#include <math.h>

// Problem dims
#define Vn 8000
#define Bn 64
#define Tn 256
#define Rn 1024
#define Un 512
#define Sn 1024
#define NROWS (Bn * Tn)  // 16384

#define NCTA 128

// scan smem layout (bytes): chunk = 64 rows x 256 cols bf16, row stride 264 elems
#define CH_COLS   256
#define ROW_STR   264                   // elems; 528 B = 33 x 16B lines (conflict-free)
#define BUF_BYTES (64 * ROW_STR * 2)    // 33792
#define OFF_BUF0  0
#define OFF_BUF1  BUF_BYTES
#define OFF_HRAW  (2 * BUF_BYTES)               // 67584
#define OFF_TRAW  (OFF_HRAW + 64 * 9 * 4)       // 69888
#define OFF_BAR   (OFF_TRAW + 64 * 9 * 4)       // 72192
#define SCAN_SMEM (OFF_BAR + 32)                // 72224

// ---------------- device scratch (static globals; no runtime allocation) ----
__device__ float g_states[Tn * Bn * Rn];   // [t][b][r] fp32 final states
__device__ float g_tmpA[Bn * Rn];
__device__ float g_tmpB[Bn * Rn];
__device__ float g_zero[Bn * Rn];
__device__ float g_outputs[NROWS * Un];
__device__ float g_slog[NROWS * Sn];
__device__ float g_tlog[NROWS];
__device__ float g_Ws[Sn * Un];
__device__ float g_svec[Sn];
__device__ int   g_sid[Sn];

// bf16 scan data
__device__ __nv_bfloat16 g_xb[NROWS * Un];                    // [t][b][u]
__device__ __nv_bfloat16 g_WbH[1024 * 1536 + 2 * 1024 * 1024]; // [j][k] x3 layers
__device__ __nv_bfloat16 g_WbT[1024 * 1536 + 2 * 1024 * 1024];
__device__ __nv_bfloat16 g_sB[2 * Bn * Rn];                   // ping-pong bf16 state
__device__ __nv_bfloat16 g_tmpA_B[Bn * Rn];
__device__ __nv_bfloat16 g_tmpB_B[Bn * Rn];

// grid barrier state
__device__ unsigned g_barCount;
__device__ unsigned g_barGen;

// ---------------- helpers ---------------------------------------------------
__device__ __forceinline__ unsigned to_tf32(float x) {
    unsigned r;
    asm("cvt.rna.tf32.f32 %0, %1;" : "=r"(r) : "f"(x));
    return r;
}

__device__ __forceinline__ void mma8(float c[4],
                                     unsigned a0, unsigned a1, unsigned a2, unsigned a3,
                                     unsigned b0, unsigned b1) {
    asm volatile(
        "mma.sync.aligned.m16n8k8.row.col.f32.tf32.tf32.f32 "
        "{%0,%1,%2,%3},{%4,%5,%6,%7},{%8,%9},{%0,%1,%2,%3};"
        : "+f"(c[0]), "+f"(c[1]), "+f"(c[2]), "+f"(c[3])
        : "r"(a0), "r"(a1), "r"(a2), "r"(a3), "r"(b0), "r"(b1));
}

__device__ __forceinline__ void mma_bf16(float c[4],
                                         unsigned a0, unsigned a1, unsigned a2, unsigned a3,
                                         unsigned b0, unsigned b1) {
    asm volatile(
        "mma.sync.aligned.m16n8k16.row.col.f32.bf16.bf16.f32 "
        "{%0,%1,%2,%3},{%4,%5,%6,%7},{%8,%9},{%0,%1,%2,%3};"
        : "+f"(c[0]), "+f"(c[1]), "+f"(c[2]), "+f"(c[3])
        : "r"(a0), "r"(a1), "r"(a2), "r"(a3), "r"(b0), "r"(b1));
}

// one 8x8-tile x4 ldmatrix (A fragment for m16n8k16)
__device__ __forceinline__ void ldsm4(unsigned& a0, unsigned& a1,
                                      unsigned& a2, unsigned& a3, unsigned addr) {
    asm volatile("ldmatrix.sync.aligned.m8n8.x4.shared.b16 {%0,%1,%2,%3}, [%4];"
                 : "=r"(a0), "=r"(a1), "=r"(a2), "=r"(a3) : "r"(addr));
}

__device__ __forceinline__ void waitBar(unsigned barU, unsigned parity) {
    asm volatile(
        "{\n\t.reg .pred P;\n\t"
        "WB_%=:\n\t"
        "mbarrier.try_wait.parity.acquire.cta.shared::cta.b64 P, [%0], %1, 0x989680;\n\t"
        "@!P bra WB_%=;\n\t}"
        :: "r"(barU), "r"(parity) : "memory");
}

// issue one chunk: 64 rows x 512 B via TMA bulk, completion on mbar
__device__ __forceinline__ void issueChunk(unsigned bufU,
    const __nv_bfloat16* src, int strideElems, unsigned barU, int tid)
{
    if (tid < 64) {
        asm volatile("mbarrier.arrive.expect_tx.shared.b64 _, [%0], %1;"
                     :: "r"(barU), "r"(512) : "memory");
        unsigned dst = bufU + (unsigned)tid * (ROW_STR * 2);
        const void* s = src + (size_t)tid * strideElems;
        asm volatile(
            "cp.async.bulk.shared::cluster.global.mbarrier::complete_tx::bytes "
            "[%0], [%1], %2, [%3];"
            :: "r"(dst), "l"(s), "r"(512), "r"(barU) : "memory");
    }
}

// ---------------- init ------------------------------------------------------
__global__ void __launch_bounds__(256) init_kernel(
    const int* __restrict__ sampled, const float* __restrict__ scnt,
    const float* __restrict__ sw, const float* __restrict__ sb,
    float* __restrict__ out)
{
    int gt = blockIdx.x * blockDim.x + threadIdx.x;
    int stride = gridDim.x * blockDim.x;
    if (gt == 0) { out[0] = 0.0f; g_barCount = 0u; g_barGen = 0u; }
    unsigned* sb32 = (unsigned*)g_sB;   // 2*Bn*Rn bf16 == Bn*Rn words
    for (int i = gt; i < Bn * Rn; i += stride) { g_zero[i] = 0.0f; sb32[i] = 0u; }
    for (int j = gt; j < Sn; j += stride) {
        int id = sampled[j];
        g_sid[j] = id;
        g_svec[j] = sb[id] - logf(scnt[j]);
    }
    for (int i = gt; i < Sn * Un; i += stride)
        g_Ws[i] = sw[(size_t)sampled[i >> 9] * Un + (i & 511)];
}

// ---------------- weight transpose/convert: f32 [K][1024] -> bf16 [1024][K] -
__global__ void __launch_bounds__(256) wconv_kernel(
    const float* __restrict__ src, int which, size_t dstOff, int K)
{
    __shared__ float tile[32][33];
    __nv_bfloat16* dst = (which ? g_WbT : g_WbH) + dstOff;
    int k0 = blockIdx.x * 32, j0 = blockIdx.y * 32;
    int tx = threadIdx.x & 31, ty = threadIdx.x >> 5;   // ty 0..7
    for (int r = ty; r < 32; r += 8)
        tile[r][tx] = src[(size_t)(k0 + r) * 1024 + j0 + tx];
    __syncthreads();
    for (int r = ty; r < 32; r += 8)
        dst[(size_t)(j0 + r) * K + k0 + tx] = __float2bfloat16_rn(tile[tx][r]);
}

// ---------------- emb pre-gather: g_xb[t*64+b][u] = bf16(emb[tok][u]) -------
__global__ void __launch_bounds__(128) xconv_kernel(
    const int* __restrict__ inp, const float* __restrict__ emb)
{
    int idx = blockIdx.x;               // t*64 + b
    int b = idx & 63, t = idx >> 6;
    int tok = inp[b * Tn + t];
    const float4* s = (const float4*)(emb + (size_t)tok * Un);
    __nv_bfloat162* d2 = (__nv_bfloat162*)(g_xb + (size_t)idx * Un);
    int v = threadIdx.x;                // 128 threads x 1 float4 = 512 elems
    float4 f = s[v];
    __nv_bfloat162 p0, p1;
    p0.x = __float2bfloat16_rn(f.x); p0.y = __float2bfloat16_rn(f.y);
    p1.x = __float2bfloat16_rn(f.z); p1.y = __float2bfloat16_rn(f.w);
    d2[2 * v] = p0;
    d2[2 * v + 1] = p1;
}

// ---------------- persistent scan kernel ------------------------------------
__device__ __forceinline__ void gridBarrier(unsigned want) {
    __threadfence();
    __syncthreads();
    if (threadIdx.x == 0) {
        unsigned t = atomicAdd(&g_barCount, 1u);
        if (t == NCTA - 1) {
            g_barCount = 0u;
            __threadfence();
            atomicExch(&g_barGen, want);
        } else {
            while (*((volatile unsigned*)&g_barGen) < want) __nanosleep(64);
        }
        __threadfence();
    }
    __syncthreads();
}

// chunk source resolution for layer-0 (emb first 512 cols) vs pure-state layers
__device__ __forceinline__ void chunkSrc(const __nv_bfloat16* aEmb,
    const __nv_bfloat16* aState, int c, const __nv_bfloat16*& src, int& strideElems)
{
    int k0 = c * CH_COLS;
    if (aEmb != nullptr && k0 < Un) { src = aEmb + k0;  strideElems = Un; }
    else {
        int kk = (aEmb != nullptr) ? (k0 - Un) : k0;
        src = aState + kk;  strideElems = Rn;
    }
}

__device__ void doPhase(
    int K,
    const __nv_bfloat16* __restrict__ WH, const __nv_bfloat16* __restrict__ WT,
    const __nv_bfloat16* __restrict__ aEmb,    // nullable: first 512 cols
    const __nv_bfloat16* __restrict__ aState,  // remaining cols
    const float* __restrict__ sF,
    const float* __restrict__ bhp, const float* __restrict__ btp,
    float* __restrict__ dstF, __nv_bfloat16* __restrict__ dstB,
    float* hraw, float* traw,
    unsigned smemU, unsigned& ph0, unsigned& ph1,
    int jbase, int tid, int w, int lane)
{
    const int g = lane >> 2, tig = lane & 3;
    const int mat = w >> 2, rbase = (w & 3) * 16;
    const int NCH = K / CH_COLS;

    // ldmatrix lane address: rows (rbase + lane&15), k-offset (lane>=16 ? 8 : 0)
    const unsigned lmOff = (unsigned)(((rbase + (lane & 15)) * ROW_STR
                                       + ((lane >> 4) << 3)) * 2);
    const unsigned buf0U = smemU + OFF_BUF0, buf1U = smemU + OFF_BUF1;
    const unsigned bar0U = smemU + OFF_BAR,  bar1U = smemU + OFF_BAR + 8;

    float acc0[4] = {0.f, 0.f, 0.f, 0.f}, acc1[4] = {0.f, 0.f, 0.f, 0.f};
    const unsigned* bw = (const unsigned*)((mat ? WT : WH) + (size_t)(jbase + g) * K);

    {
        const __nv_bfloat16* src; int st;
        chunkSrc(aEmb, aState, 0, src, st);
        issueChunk(buf0U, src, st, bar0U, tid);
    }

    for (int c = 0; c < NCH; c++) {
        unsigned barU = (c & 1) ? bar1U : bar0U;
        unsigned par  = (c & 1) ? ph1 : ph0;
        waitBar(barU, par);
        if (c & 1) ph1 ^= 1u; else ph0 ^= 1u;

        if (c + 1 < NCH) {
            __syncthreads();   // all warps done reading buf[(c+1)&1] (chunk c-1)
            const __nv_bfloat16* src; int st;
            chunkSrc(aEmb, aState, c + 1, src, st);
            issueChunk(((c + 1) & 1) ? buf1U : buf0U, src, st,
                       ((c + 1) & 1) ? bar1U : bar0U, tid);
        }

        unsigned aAddr = ((c & 1) ? buf1U : buf0U) + lmOff;
        const unsigned* br = bw + (c << 7) + tig;   // c*256/2 unsigned units
        #pragma unroll
        for (int s = 0; s < 16; s++) {              // 16 k16-steps per chunk
            unsigned a0, a1, a2, a3;
            ldsm4(a0, a1, a2, a3, aAddr + s * 32);
            unsigned b0 = __ldg(br + s * 8), b1 = __ldg(br + s * 8 + 4);
            if (s & 1) mma_bf16(acc1, a0, a1, a2, a3, b0, b1);
            else       mma_bf16(acc0, a0, a1, a2, a3, b0, b1);
        }
    }

    float* raw = mat ? traw : hraw;
    int r0 = rbase + g;
    raw[r0 * 9 + 2 * tig]           = acc0[0] + acc1[0];
    raw[r0 * 9 + 2 * tig + 1]       = acc0[1] + acc1[1];
    raw[(r0 + 8) * 9 + 2 * tig]     = acc0[2] + acc1[2];
    raw[(r0 + 8) * 9 + 2 * tig + 1] = acc0[3] + acc1[3];
    __syncthreads();
    #pragma unroll
    for (int r = 0; r < 2; r++) {
        int v = tid + r * 256;
        int b = v >> 3, jj = v & 7, j = jbase + jj;
        float hpre = hraw[b * 9 + jj] + __ldg(&bhp[j]);
        float tpre = traw[b * 9 + jj] + __ldg(&btp[j]);
        float s = __ldcg(&sF[b * Rn + j]);
        float tg = 1.0f / (1.0f + __expf(-tpre));
        float o = (tanhf(hpre) - s) * tg + s;
        dstF[b * Rn + j] = o;
        dstB[b * Rn + j] = __float2bfloat16_rn(o);
    }
}

__global__ void __launch_bounds__(256) scan_kernel(
    const float* __restrict__ bh0, const float* __restrict__ bt0,
    const float* __restrict__ bh, const float* __restrict__ bt)
{
    extern __shared__ char smem[];
    const unsigned smemU = (unsigned)__cvta_generic_to_shared(smem);
    float* hraw = (float*)(smem + OFF_HRAW);
    float* traw = (float*)(smem + OFF_TRAW);

    const int tid = threadIdx.x, w = tid >> 5, lane = tid & 31;
    const int jbase = blockIdx.x * 8;
    const size_t OFF1 = (size_t)1024 * 1536;
    const size_t OFF2 = OFF1 + (size_t)1024 * 1024;

    if (tid == 0) {
        asm volatile("mbarrier.init.shared.b64 [%0], 64;" :: "r"(smemU + OFF_BAR) : "memory");
        asm volatile("mbarrier.init.shared.b64 [%0], 64;" :: "r"(smemU + OFF_BAR + 8) : "memory");
    }
    __syncthreads();

    unsigned ph0 = 0u, ph1 = 0u;
    unsigned want = 0;
    for (int t = 0; t < Tn; t++) {
        const __nv_bfloat16* xbt    = g_xb + (size_t)t * Bn * Un;
        const __nv_bfloat16* sBprev = g_sB + (size_t)((t + 1) & 1) * Bn * Rn;
        const float* sFprev = (t == 0) ? g_zero : (g_states + (size_t)(t - 1) * Bn * Rn);

        doPhase(1536, g_WbH, g_WbT, xbt, sBprev, sFprev, bh0, bt0,
                g_tmpA, g_tmpA_B, hraw, traw, smemU, ph0, ph1, jbase, tid, w, lane);
        gridBarrier(++want);
        doPhase(1024, g_WbH + OFF1, g_WbT + OFF1, nullptr, g_tmpA_B, g_tmpA,
                bh, bt, g_tmpB, g_tmpB_B, hraw, traw, smemU, ph0, ph1, jbase, tid, w, lane);
        gridBarrier(++want);
        doPhase(1024, g_WbH + OFF2, g_WbT + OFF2, nullptr, g_tmpB_B, g_tmpB,
                bh + Rn, bt + Rn,
                g_states + (size_t)t * Bn * Rn, g_sB + (size_t)(t & 1) * Bn * Rn,
                hraw, traw, smemU, ph0, ph1, jbase, tid, w, lane);
        gridBarrier(++want);
    }
}

// ---------------- projection: outputs[m][u] = states . Wp + bp --------------
__global__ void __launch_bounds__(256) proj_kernel(
    const float* __restrict__ Wp, const float* __restrict__ bp)
{
    __shared__ float AS[64][33];
    __shared__ float BS[32][65];

    const int tid = threadIdx.x;
    const int warp = tid >> 5, lane = tid & 31;
    const int g = lane >> 2, tig = lane & 3;
    const int rbase = (warp >> 1) * 16;
    const int cbase = (warp & 1) * 32;
    const int m0 = blockIdx.x * 64, jb = blockIdx.y * 64;

    float c[4][4];
    #pragma unroll
    for (int nt = 0; nt < 4; nt++)
        #pragma unroll
        for (int i = 0; i < 4; i++) c[nt][i] = 0.f;

    for (int t0 = 0; t0 < Rn; t0 += 32) {
        #pragma unroll
        for (int r = 0; r < 2; r++) {
            int v = r * 256 + tid;
            int row = v >> 3, q = v & 7;
            int m = m0 + row;
            const float* p = g_states + (size_t)(m & (Tn - 1)) * (Bn * Rn)
                                      + (size_t)(m >> 8) * Rn + t0 + q * 4;
            float4 f = *(const float4*)p;
            AS[row][q*4+0] = __uint_as_float(to_tf32(f.x));
            AS[row][q*4+1] = __uint_as_float(to_tf32(f.y));
            AS[row][q*4+2] = __uint_as_float(to_tf32(f.z));
            AS[row][q*4+3] = __uint_as_float(to_tf32(f.w));
        }
        #pragma unroll
        for (int r = 0; r < 2; r++) {
            int v = r * 256 + tid;
            int kk = v >> 4, jq = v & 15;
            float4 f = *(const float4*)(Wp + (size_t)(t0 + kk) * Un + jb + jq * 4);
            BS[kk][jq*4+0] = __uint_as_float(to_tf32(f.x));
            BS[kk][jq*4+1] = __uint_as_float(to_tf32(f.y));
            BS[kk][jq*4+2] = __uint_as_float(to_tf32(f.z));
            BS[kk][jq*4+3] = __uint_as_float(to_tf32(f.w));
        }
        __syncthreads();

        #pragma unroll
        for (int k8 = 0; k8 < 32; k8 += 8) {
            unsigned a0 = __float_as_uint(AS[rbase + g    ][k8 + tig    ]);
            unsigned a1 = __float_as_uint(AS[rbase + g + 8][k8 + tig    ]);
            unsigned a2 = __float_as_uint(AS[rbase + g    ][k8 + tig + 4]);
            unsigned a3 = __float_as_uint(AS[rbase + g + 8][k8 + tig + 4]);
            #pragma unroll
            for (int nt = 0; nt < 4; nt++) {
                int j = cbase + nt * 8 + g;
                unsigned b0 = __float_as_uint(BS[k8 + tig    ][j]);
                unsigned b1 = __float_as_uint(BS[k8 + tig + 4][j]);
                mma8(c[nt], a0, a1, a2, a3, b0, b1);
            }
        }
        __syncthreads();
    }

    #pragma unroll
    for (int nt = 0; nt < 4; nt++) {
        #pragma unroll
        for (int i = 0; i < 4; i++) {
            int m = m0 + rbase + g + ((i >= 2) ? 8 : 0);
            int j = jb + cbase + nt * 8 + tig * 2 + (i & 1);
            g_outputs[(size_t)m * Un + j] = c[nt][i] + bp[j];
        }
    }
}

// ---------------- sampled logits: outputs @ Ws^T + svec, hit mask -----------
__global__ void __launch_bounds__(256) slog_kernel(const int* __restrict__ labels)
{
    __shared__ float AS[64][33];
    __shared__ float BS[32][65];

    const int tid = threadIdx.x;
    const int warp = tid >> 5, lane = tid & 31;
    const int g = lane >> 2, tig = lane & 3;
    const int rbase = (warp >> 1) * 16;
    const int cbase = (warp & 1) * 32;
    const int m0 = blockIdx.x * 64, jb = blockIdx.y * 64;

    float c[4][4];
    #pragma unroll
    for (int nt = 0; nt < 4; nt++)
        #pragma unroll
        for (int i = 0; i < 4; i++) c[nt][i] = 0.f;

    for (int t0 = 0; t0 < Un; t0 += 32) {
        #pragma unroll
        for (int r = 0; r < 2; r++) {
            int v = r * 256 + tid;
            int row = v >> 3, q = v & 7;
            const float* p = g_outputs + (size_t)(m0 + row) * Un + t0 + q * 4;
            float4 f = *(const float4*)p;
            AS[row][q*4+0] = __uint_as_float(to_tf32(f.x));
            AS[row][q*4+1] = __uint_as_float(to_tf32(f.y));
            AS[row][q*4+2] = __uint_as_float(to_tf32(f.z));
            AS[row][q*4+3] = __uint_as_float(to_tf32(f.w));
        }
        #pragma unroll
        for (int r = 0; r < 2; r++) {
            int v = r * 256 + tid;
            int j = v >> 3, q = v & 7;
            float4 f = *(const float4*)(g_Ws + (size_t)(jb + j) * Un + t0 + q * 4);
            BS[q*4+0][j] = __uint_as_float(to_tf32(f.x));
            BS[q*4+1][j] = __uint_as_float(to_tf32(f.y));
            BS[q*4+2][j] = __uint_as_float(to_tf32(f.z));
            BS[q*4+3][j] = __uint_as_float(to_tf32(f.w));
        }
        __syncthreads();

        #pragma unroll
        for (int k8 = 0; k8 < 32; k8 += 8) {
            unsigned a0 = __float_as_uint(AS[rbase + g    ][k8 + tig    ]);
            unsigned a1 = __float_as_uint(AS[rbase + g + 8][k8 + tig    ]);
            unsigned a2 = __float_as_uint(AS[rbase + g    ][k8 + tig + 4]);
            unsigned a3 = __float_as_uint(AS[rbase + g + 8][k8 + tig + 4]);
            #pragma unroll
            for (int nt = 0; nt < 4; nt++) {
                int j = cbase + nt * 8 + g;
                unsigned b0 = __float_as_uint(BS[k8 + tig    ][j]);
                unsigned b1 = __float_as_uint(BS[k8 + tig + 4][j]);
                mma8(c[nt], a0, a1, a2, a3, b0, b1);
            }
        }
        __syncthreads();
    }

    #pragma unroll
    for (int nt = 0; nt < 4; nt++) {
        #pragma unroll
        for (int i = 0; i < 4; i++) {
            int m = m0 + rbase + g + ((i >= 2) ? 8 : 0);
            int j = jb + cbase + nt * 8 + tig * 2 + (i & 1);
            float v = c[nt][i] + g_svec[j];
            if (labels[m] == g_sid[j]) v -= 1e9f;
            g_slog[(size_t)m * Sn + j] = v;
        }
    }
}

// ---------------- true logits: warp per row ---------------------------------
__global__ void __launch_bounds__(256) tlog_kernel(
    const int* __restrict__ labels, const float* __restrict__ sw,
    const float* __restrict__ sb, const float* __restrict__ tcnt)
{
    int warp = threadIdx.x >> 5, lane = threadIdx.x & 31;
    int n = blockIdx.x * 8 + warp;
    int lab = labels[n];
    const float4* o = (const float4*)(g_outputs + (size_t)n * Un);
    const float4* w = (const float4*)(sw + (size_t)lab * Un);
    float acc = 0.f;
    #pragma unroll
    for (int q = 0; q < 4; q++) {
        float4 a = o[lane + q * 32];
        float4 b = w[lane + q * 32];
        acc += a.x * b.x + a.y * b.y + a.z * b.z + a.w * b.w;
    }
    #pragma unroll
    for (int s = 16; s; s >>= 1) acc += __shfl_xor_sync(0xffffffffu, acc, s);
    if (lane == 0) g_tlog[n] = acc + sb[lab] - logf(tcnt[n]);
}

// ---------------- loss: warp per row, online logsumexp ----------------------
__global__ void __launch_bounds__(256) loss_kernel(float* __restrict__ out)
{
    __shared__ float red[8];
    int warp = threadIdx.x >> 5, lane = threadIdx.x & 31;
    int n = blockIdx.x * 8 + warp;

    float mL = -INFINITY, sL = 0.f;
    const float* row = g_slog + (size_t)n * Sn;
    for (int j = lane; j < Sn; j += 32) {
        float v = row[j];
        if (v > mL) { sL = sL * __expf(mL - v) + 1.f; mL = v; }
        else          sL += __expf(v - mL);
    }
    #pragma unroll
    for (int s = 16; s; s >>= 1) {
        float m2 = __shfl_xor_sync(0xffffffffu, mL, s);
        float s2 = __shfl_xor_sync(0xffffffffu, sL, s);
        float M = fmaxf(mL, m2);
        sL = sL * __expf(mL - M) + s2 * __expf(m2 - M);
        mL = M;
    }
    float z0 = g_tlog[n];
    float M = fmaxf(mL, z0);
    float S = sL * __expf(mL - M) + __expf(z0 - M);
    float loss = (M + logf(S)) - z0;

    if (lane == 0) red[warp] = loss;
    __syncthreads();
    if (threadIdx.x == 0) {
        float t = 0.f;
        #pragma unroll
        for (int i = 0; i < 8; i++) t += red[i];
        atomicAdd(out, t * (1.0f / NROWS));
    }
}

// ---------------- launch ----------------------------------------------------
extern "C" void kernel_launch(void* const* d_in, const int* in_sizes, int n_in,
                              void* d_out, int out_size)
{
    (void)in_sizes; (void)n_in; (void)out_size;

    const int*   input   = (const int*)  d_in[0];
    const int*   targets = (const int*)  d_in[1];
    const int*   sampled = (const int*)  d_in[2];
    const float* tcnt    = (const float*)d_in[3];
    const float* scnt    = (const float*)d_in[4];
    const float* emb     = (const float*)d_in[5];
    const float* Wh0     = (const float*)d_in[6];
    const float* bh0     = (const float*)d_in[7];
    const float* Wt0     = (const float*)d_in[8];
    const float* bt0     = (const float*)d_in[9];
    const float* Wh      = (const float*)d_in[10];
    const float* bh      = (const float*)d_in[11];
    const float* Wt      = (const float*)d_in[12];
    const float* bt      = (const float*)d_in[13];
    const float* Wp      = (const float*)d_in[14];
    const float* bp      = (const float*)d_in[15];
    const float* sw      = (const float*)d_in[16];
    const float* sb      = (const float*)d_in[17];
    float* out = (float*)d_out;

    const size_t OFF1 = (size_t)1024 * 1536;
    const size_t OFF2 = OFF1 + (size_t)1024 * 1024;

    static int smemSet = 0;
    if (!smemSet) {
        cudaFuncSetAttribute(scan_kernel,
                             cudaFuncAttributeMaxDynamicSharedMemorySize, SCAN_SMEM);
        smemSet = 1;
    }

    init_kernel<<<256, 256>>>(sampled, scnt, sw, sb, out);

    // weight transpose/convert (once per run; inside graph for determinism)
    wconv_kernel<<<dim3(48, 32), 256>>>(Wh0, 0, 0, 1536);
    wconv_kernel<<<dim3(48, 32), 256>>>(Wt0, 1, 0, 1536);
    wconv_kernel<<<dim3(32, 32), 256>>>(Wh,                   0, OFF1, 1024);
    wconv_kernel<<<dim3(32, 32), 256>>>(Wt,                   1, OFF1, 1024);
    wconv_kernel<<<dim3(32, 32), 256>>>(Wh + (size_t)Rn * Rn, 0, OFF2, 1024);
    wconv_kernel<<<dim3(32, 32), 256>>>(Wt + (size_t)Rn * Rn, 1, OFF2, 1024);

    xconv_kernel<<<NROWS, 128>>>(input, emb);

    // the whole 256-step x 3-layer scan in ONE persistent kernel
    scan_kernel<<<NCTA, 256, SCAN_SMEM>>>(bh0, bt0, bh, bt);

    proj_kernel<<<dim3(NROWS / 64, Un / 64), 256>>>(Wp, bp);
    slog_kernel<<<dim3(NROWS / 64, Sn / 64), 256>>>(targets);
    tlog_kernel<<<NROWS / 8, 256>>>(targets, sw, sb, tcnt);
    loss_kernel<<<NROWS / 8, 256>>>(out);
}

// round 11
// speedup vs baseline: 5.5581x; 1.2979x over previous
#include <cuda_runtime.h>
#include <cuda_bf16.h>
#include <math.h>

// Problem dims
#define Vn 8000
#define Bn 64
#define Tn 256
#define Rn 1024
#define Un 512
#define Sn 1024
#define NROWS (Bn * Tn)  // 16384

#define NCTA 128
#define CH_COLS 256
#define ROW_STR 264                      // elems; 528 B rows, conflict-free for ldsm

// smem W section offsets (elems). col stride = K+8 elems.
#define L0H 0
#define L0T 12352
#define L1H 24704
#define L1T 32960
#define L2H 41216
#define L2T 49472
#define W_ELEMS 57728                    // 115456 B

// smem byte layout
#define OFF_BUF0 115456
#define OFF_BUF1 149248                  // +64*264*2
#define OFF_HRAW 183040
#define OFF_TRAW 185344
#define OFF_BAR  187648
#define SCAN_SMEM 187712

// ---------------- device scratch (static globals; no runtime allocation) ----
__device__ float g_states[Tn * Bn * Rn];   // [t][b][r] fp32 final states (for proj)
__device__ float g_outputs[NROWS * Un];
__device__ float g_slog[NROWS * Sn];
__device__ float g_tlog[NROWS];
__device__ float g_Ws[Sn * Un];
__device__ float g_svec[Sn];
__device__ int   g_sid[Sn];

// bf16 scan data
__device__ __nv_bfloat16 g_xb[NROWS * Un];                     // [t][b][u]
__device__ __nv_bfloat16 g_WbH[1024 * 1536 + 2 * 1024 * 1024]; // [j][k] x3 layers
__device__ __nv_bfloat16 g_WbT[1024 * 1536 + 2 * 1024 * 1024];
__device__ __nv_bfloat16 g_sB[2 * Bn * Rn];                    // ping-pong L2-out
__device__ __nv_bfloat16 g_tmpA_B[Bn * Rn];                    // L0 out
__device__ __nv_bfloat16 g_tmpB_B[Bn * Rn];                    // L1 out

// per-(phase,group) producer counters: monotonic within one launch
__device__ unsigned g_cnt[768 * 4];

// ---------------- helpers ---------------------------------------------------
__device__ __forceinline__ unsigned to_tf32(float x) {
    unsigned r;
    asm("cvt.rna.tf32.f32 %0, %1;" : "=r"(r) : "f"(x));
    return r;
}

__device__ __forceinline__ void mma8(float c[4],
                                     unsigned a0, unsigned a1, unsigned a2, unsigned a3,
                                     unsigned b0, unsigned b1) {
    asm volatile(
        "mma.sync.aligned.m16n8k8.row.col.f32.tf32.tf32.f32 "
        "{%0,%1,%2,%3},{%4,%5,%6,%7},{%8,%9},{%0,%1,%2,%3};"
        : "+f"(c[0]), "+f"(c[1]), "+f"(c[2]), "+f"(c[3])
        : "r"(a0), "r"(a1), "r"(a2), "r"(a3), "r"(b0), "r"(b1));
}

__device__ __forceinline__ void mma_bf16(float c[4],
                                         unsigned a0, unsigned a1, unsigned a2, unsigned a3,
                                         unsigned b0, unsigned b1) {
    asm volatile(
        "mma.sync.aligned.m16n8k16.row.col.f32.bf16.bf16.f32 "
        "{%0,%1,%2,%3},{%4,%5,%6,%7},{%8,%9},{%0,%1,%2,%3};"
        : "+f"(c[0]), "+f"(c[1]), "+f"(c[2]), "+f"(c[3])
        : "r"(a0), "r"(a1), "r"(a2), "r"(a3), "r"(b0), "r"(b1));
}

__device__ __forceinline__ void ldsm4(unsigned& a0, unsigned& a1,
                                      unsigned& a2, unsigned& a3, unsigned addr) {
    asm volatile("ldmatrix.sync.aligned.m8n8.x4.shared.b16 {%0,%1,%2,%3}, [%4];"
                 : "=r"(a0), "=r"(a1), "=r"(a2), "=r"(a3) : "r"(addr));
}

__device__ __forceinline__ void waitBar(unsigned barU, unsigned parity) {
    asm volatile(
        "{\n\t.reg .pred P;\n\t"
        "WB_%=:\n\t"
        "mbarrier.try_wait.parity.acquire.cta.shared::cta.b64 P, [%0], %1, 0x989680;\n\t"
        "@!P bra WB_%=;\n\t}"
        :: "r"(barU), "r"(parity) : "memory");
}

__device__ __forceinline__ void waitCnt(int idx, int tid) {
    if (tid < 64) {
        const unsigned* p = &g_cnt[idx];
        unsigned v;
        for (;;) {
            asm volatile("ld.global.cg.u32 %0, [%1];" : "=r"(v) : "l"(p));
            if (v >= 32u) break;
            __nanosleep(32);
        }
    }
}

// issue one chunk: 64 rows x 512 B via TMA bulk, completion on mbar
__device__ __forceinline__ void issueChunk(unsigned bufU,
    const __nv_bfloat16* src, int strideElems, unsigned barU, int tid)
{
    if (tid < 64) {
        asm volatile("mbarrier.arrive.expect_tx.shared.b64 _, [%0], %1;"
                     :: "r"(barU), "r"(512) : "memory");
        unsigned dst = bufU + (unsigned)tid * (ROW_STR * 2);
        const void* s = src + (size_t)tid * strideElems;
        asm volatile(
            "cp.async.bulk.shared::cluster.global.mbarrier::complete_tx::bytes "
            "[%0], [%1], %2, [%3];"
            :: "r"(dst), "l"(s), "r"(512), "r"(barU) : "memory");
    }
}

// chunk source resolution
__device__ __forceinline__ void chunkSrc(const __nv_bfloat16* aEmb,
    const __nv_bfloat16* aState, int c, int waitPhase,
    const __nv_bfloat16*& src, int& strideElems, int& waitIdx)
{
    int k0 = c * CH_COLS;
    if (aEmb != nullptr && k0 < Un) {
        src = aEmb + k0; strideElems = Un; waitIdx = -1;
    } else {
        int kk = (aEmb != nullptr) ? (k0 - Un) : k0;
        src = aState + kk; strideElems = Rn;
        waitIdx = (waitPhase >= 0) ? (waitPhase * 4 + (kk >> 8)) : -1;
    }
}

// ---------------- init ------------------------------------------------------
__global__ void __launch_bounds__(256) init_kernel(
    const int* __restrict__ sampled, const float* __restrict__ scnt,
    const float* __restrict__ sw, const float* __restrict__ sb,
    float* __restrict__ out)
{
    int gt = blockIdx.x * blockDim.x + threadIdx.x;
    int stride = gridDim.x * blockDim.x;
    if (gt == 0) out[0] = 0.0f;
    unsigned* sb32 = (unsigned*)g_sB;   // both ping-pong slots as words
    for (int i = gt; i < Bn * Rn; i += stride) sb32[i] = 0u;
    for (int i = gt; i < 768 * 4; i += stride) g_cnt[i] = 0u;
    for (int j = gt; j < Sn; j += stride) {
        int id = sampled[j];
        g_sid[j] = id;
        g_svec[j] = sb[id] - logf(scnt[j]);
    }
    for (int i = gt; i < Sn * Un; i += stride)
        g_Ws[i] = sw[(size_t)sampled[i >> 9] * Un + (i & 511)];
}

// ---------------- weight transpose/convert: f32 [K][1024] -> bf16 [1024][K] -
__global__ void __launch_bounds__(256) wconv_kernel(
    const float* __restrict__ src, int which, size_t dstOff, int K)
{
    __shared__ float tile[32][33];
    __nv_bfloat16* dst = (which ? g_WbT : g_WbH) + dstOff;
    int k0 = blockIdx.x * 32, j0 = blockIdx.y * 32;
    int tx = threadIdx.x & 31, ty = threadIdx.x >> 5;
    for (int r = ty; r < 32; r += 8)
        tile[r][tx] = src[(size_t)(k0 + r) * 1024 + j0 + tx];
    __syncthreads();
    for (int r = ty; r < 32; r += 8)
        dst[(size_t)(j0 + r) * K + k0 + tx] = __float2bfloat16_rn(tile[tx][r]);
}

// ---------------- emb pre-gather --------------------------------------------
__global__ void __launch_bounds__(128) xconv_kernel(
    const int* __restrict__ inp, const float* __restrict__ emb)
{
    int idx = blockIdx.x;               // t*64 + b
    int b = idx & 63, t = idx >> 6;
    int tok = inp[b * Tn + t];
    const float4* s = (const float4*)(emb + (size_t)tok * Un);
    __nv_bfloat162* d2 = (__nv_bfloat162*)(g_xb + (size_t)idx * Un);
    int v = threadIdx.x;
    float4 f = s[v];
    __nv_bfloat162 p0, p1;
    p0.x = __float2bfloat16_rn(f.x); p0.y = __float2bfloat16_rn(f.y);
    p1.x = __float2bfloat16_rn(f.z); p1.y = __float2bfloat16_rn(f.w);
    d2[2 * v] = p0;
    d2[2 * v + 1] = p1;
}

// ---------------- one highway phase (dual GEMM + gate) ----------------------
__device__ void doPhase(
    int K, int pIdx, int waitPhase,
    int offHElems, int offTElems,
    const __nv_bfloat16* __restrict__ aEmb,
    const __nv_bfloat16* __restrict__ aState,
    float biasH, float biasT,
    float& s0, float& s1,
    __nv_bfloat16* __restrict__ dstB,
    float* __restrict__ stF,           // nullable (layer 2 only)
    char* smem, unsigned smemU,
    unsigned& ph0, unsigned& ph1,
    int jbase, int tid, int w, int lane)
{
    const int g = lane >> 2, tig = lane & 3;
    const int mat = w >> 2, rbase = (w & 3) * 16;
    const int NCH = K / CH_COLS;
    const int strW = K + 8;

    const unsigned lmOff = (unsigned)(((rbase + (lane & 15)) * ROW_STR
                                       + ((lane >> 4) << 3)) * 2);
    const unsigned buf0U = smemU + OFF_BUF0, buf1U = smemU + OFF_BUF1;
    const unsigned bar0U = smemU + OFF_BAR,  bar1U = smemU + OFF_BAR + 8;

    float acc0[4] = {0.f, 0.f, 0.f, 0.f}, acc1[4] = {0.f, 0.f, 0.f, 0.f};
    const unsigned* bw = (const unsigned*)((const __nv_bfloat16*)smem
                          + (mat ? offTElems : offHElems) + g * strW);

    {
        const __nv_bfloat16* src; int st, wi;
        chunkSrc(aEmb, aState, 0, waitPhase, src, st, wi);
        if (wi >= 0) waitCnt(wi, tid);
        issueChunk(buf0U, src, st, bar0U, tid);
    }

    for (int c = 0; c < NCH; c++) {
        unsigned barU = (c & 1) ? bar1U : bar0U;
        unsigned par  = (c & 1) ? ph1 : ph0;
        waitBar(barU, par);
        if (c & 1) ph1 ^= 1u; else ph0 ^= 1u;

        if (c + 1 < NCH) {
            __syncthreads();   // all warps done reading the other buffer
            const __nv_bfloat16* src; int st, wi;
            chunkSrc(aEmb, aState, c + 1, waitPhase, src, st, wi);
            if (wi >= 0) waitCnt(wi, tid);
            issueChunk(((c + 1) & 1) ? buf1U : buf0U, src, st,
                       ((c + 1) & 1) ? bar1U : bar0U, tid);
        }

        unsigned aAddr = ((c & 1) ? buf1U : buf0U) + lmOff;
        const unsigned* br = bw + (c << 7) + tig;   // c*256 elems / 2 words
        #pragma unroll
        for (int s8 = 0; s8 < 16; s8++) {
            unsigned a0, a1, a2, a3;
            ldsm4(a0, a1, a2, a3, aAddr + s8 * 32);
            unsigned b0 = br[s8 * 8], b1 = br[s8 * 8 + 4];   // conflict-free LDS
            if (s8 & 1) mma_bf16(acc1, a0, a1, a2, a3, b0, b1);
            else        mma_bf16(acc0, a0, a1, a2, a3, b0, b1);
        }
    }

    float* hraw = (float*)(smem + OFF_HRAW);
    float* traw = (float*)(smem + OFF_TRAW);
    float* raw = mat ? traw : hraw;
    int r0 = rbase + g;
    raw[r0 * 9 + 2 * tig]           = acc0[0] + acc1[0];
    raw[r0 * 9 + 2 * tig + 1]       = acc0[1] + acc1[1];
    raw[(r0 + 8) * 9 + 2 * tig]     = acc0[2] + acc1[2];
    raw[(r0 + 8) * 9 + 2 * tig + 1] = acc0[3] + acc1[3];
    __syncthreads();

    // epilogue: thread owns rows (tid>>3) and (tid>>3)+32 at col jbase+(tid&7)
    int jj = tid & 7, jcol = jbase + jj, b0r = tid >> 3;
    {
        float hp = hraw[b0r * 9 + jj] + biasH;
        float tp = traw[b0r * 9 + jj] + biasT;
        float tg = 1.0f / (1.0f + __expf(-tp));
        float o = (tanhf(hp) - s0) * tg + s0;
        s0 = o;
        dstB[b0r * Rn + jcol] = __float2bfloat16_rn(o);
        if (stF) stF[b0r * Rn + jcol] = o;
    }
    {
        int b1r = b0r + 32;
        float hp = hraw[b1r * 9 + jj] + biasH;
        float tp = traw[b1r * 9 + jj] + biasT;
        float tg = 1.0f / (1.0f + __expf(-tp));
        float o = (tanhf(hp) - s1) * tg + s1;
        s1 = o;
        dstB[b1r * Rn + jcol] = __float2bfloat16_rn(o);
        if (stF) stF[b1r * Rn + jcol] = o;
    }
    __threadfence();
    __syncthreads();
    if (tid == 0) atomicAdd(&g_cnt[pIdx * 4 + (blockIdx.x >> 5)], 1u);
}

// ---------------- persistent scan kernel ------------------------------------
__global__ void __launch_bounds__(256) scan_kernel(
    const float* __restrict__ bh0, const float* __restrict__ bt0,
    const float* __restrict__ bh, const float* __restrict__ bt)
{
    extern __shared__ char smem[];
    const unsigned smemU = (unsigned)__cvta_generic_to_shared(smem);
    const int tid = threadIdx.x, w = tid >> 5, lane = tid & 31;
    const int jbase = blockIdx.x * 8;
    const size_t GOFF1 = (size_t)1024 * 1536;
    const size_t GOFF2 = GOFF1 + (size_t)1024 * 1024;

    // preload this CTA's weight slice into smem (once)
    {
        const int Ks[6] = {1536, 1536, 1024, 1024, 1024, 1024};
        const int so[6] = {L0H, L0T, L1H, L1T, L2H, L2T};
        const size_t go[6] = {0, 0, GOFF1, GOFF1, GOFF2, GOFF2};
        __nv_bfloat16* wsm = (__nv_bfloat16*)smem;
        for (int sec = 0; sec < 6; sec++) {
            const __nv_bfloat16* gsrc = ((sec & 1) ? g_WbT : g_WbH)
                                        + go[sec] + (size_t)jbase * Ks[sec];
            int kv = Ks[sec] >> 3;            // uint4 per col
            int nv = Ks[sec];                 // 8 cols * kv
            for (int i = tid; i < nv; i += 256) {
                int col = i / kv, vi = i - col * kv;
                *(uint4*)(wsm + so[sec] + col * (Ks[sec] + 8) + vi * 8) =
                    *(const uint4*)(gsrc + (size_t)col * Ks[sec] + vi * 8);
            }
        }
    }
    if (tid == 0) {
        asm volatile("mbarrier.init.shared.b64 [%0], 64;" :: "r"(smemU + OFF_BAR) : "memory");
        asm volatile("mbarrier.init.shared.b64 [%0], 64;" :: "r"(smemU + OFF_BAR + 8) : "memory");
    }
    __syncthreads();

    // per-thread biases (col fixed across phases)
    int jcol = jbase + (tid & 7);
    float b0H = __ldg(&bh0[jcol]), b0T = __ldg(&bt0[jcol]);
    float b1H = __ldg(&bh[jcol]),  b1T = __ldg(&bt[jcol]);
    float b2H = __ldg(&bh[Rn + jcol]), b2T = __ldg(&bt[Rn + jcol]);

    float s0 = 0.f, s1 = 0.f;          // recurrent state (own cell), fp32
    unsigned ph0 = 0u, ph1 = 0u;

    for (int t = 0; t < Tn; t++) {
        const __nv_bfloat16* xbt = g_xb + (size_t)t * Bn * Un;
        const __nv_bfloat16* prevL2 = g_sB + (size_t)((t + 1) & 1) * Bn * Rn;
        int p = 3 * t;

        doPhase(1536, p, (t ? p - 1 : -1), L0H, L0T, xbt, prevL2,
                b0H, b0T, s0, s1, g_tmpA_B, nullptr,
                smem, smemU, ph0, ph1, jbase, tid, w, lane);
        doPhase(1024, p + 1, p, L1H, L1T, nullptr, g_tmpA_B,
                b1H, b1T, s0, s1, g_tmpB_B, nullptr,
                smem, smemU, ph0, ph1, jbase, tid, w, lane);
        doPhase(1024, p + 2, p + 1, L2H, L2T, nullptr, g_tmpB_B,
                b2H, b2T, s0, s1, g_sB + (size_t)(t & 1) * Bn * Rn,
                g_states + (size_t)t * Bn * Rn,
                smem, smemU, ph0, ph1, jbase, tid, w, lane);
    }
}

// ---------------- projection: outputs[m][u] = states . Wp + bp --------------
__global__ void __launch_bounds__(256) proj_kernel(
    const float* __restrict__ Wp, const float* __restrict__ bp)
{
    __shared__ float AS[64][33];
    __shared__ float BS[32][65];

    const int tid = threadIdx.x;
    const int warp = tid >> 5, lane = tid & 31;
    const int g = lane >> 2, tig = lane & 3;
    const int rbase = (warp >> 1) * 16;
    const int cbase = (warp & 1) * 32;
    const int m0 = blockIdx.x * 64, jb = blockIdx.y * 64;

    float c[4][4];
    #pragma unroll
    for (int nt = 0; nt < 4; nt++)
        #pragma unroll
        for (int i = 0; i < 4; i++) c[nt][i] = 0.f;

    for (int t0 = 0; t0 < Rn; t0 += 32) {
        #pragma unroll
        for (int r = 0; r < 2; r++) {
            int v = r * 256 + tid;
            int row = v >> 3, q = v & 7;
            int m = m0 + row;
            const float* p = g_states + (size_t)(m & (Tn - 1)) * (Bn * Rn)
                                      + (size_t)(m >> 8) * Rn + t0 + q * 4;
            float4 f = *(const float4*)p;
            AS[row][q*4+0] = __uint_as_float(to_tf32(f.x));
            AS[row][q*4+1] = __uint_as_float(to_tf32(f.y));
            AS[row][q*4+2] = __uint_as_float(to_tf32(f.z));
            AS[row][q*4+3] = __uint_as_float(to_tf32(f.w));
        }
        #pragma unroll
        for (int r = 0; r < 2; r++) {
            int v = r * 256 + tid;
            int kk = v >> 4, jq = v & 15;
            float4 f = *(const float4*)(Wp + (size_t)(t0 + kk) * Un + jb + jq * 4);
            BS[kk][jq*4+0] = __uint_as_float(to_tf32(f.x));
            BS[kk][jq*4+1] = __uint_as_float(to_tf32(f.y));
            BS[kk][jq*4+2] = __uint_as_float(to_tf32(f.z));
            BS[kk][jq*4+3] = __uint_as_float(to_tf32(f.w));
        }
        __syncthreads();

        #pragma unroll
        for (int k8 = 0; k8 < 32; k8 += 8) {
            unsigned a0 = __float_as_uint(AS[rbase + g    ][k8 + tig    ]);
            unsigned a1 = __float_as_uint(AS[rbase + g + 8][k8 + tig    ]);
            unsigned a2 = __float_as_uint(AS[rbase + g    ][k8 + tig + 4]);
            unsigned a3 = __float_as_uint(AS[rbase + g + 8][k8 + tig + 4]);
            #pragma unroll
            for (int nt = 0; nt < 4; nt++) {
                int j = cbase + nt * 8 + g;
                unsigned b0 = __float_as_uint(BS[k8 + tig    ][j]);
                unsigned b1 = __float_as_uint(BS[k8 + tig + 4][j]);
                mma8(c[nt], a0, a1, a2, a3, b0, b1);
            }
        }
        __syncthreads();
    }

    #pragma unroll
    for (int nt = 0; nt < 4; nt++) {
        #pragma unroll
        for (int i = 0; i < 4; i++) {
            int m = m0 + rbase + g + ((i >= 2) ? 8 : 0);
            int j = jb + cbase + nt * 8 + tig * 2 + (i & 1);
            g_outputs[(size_t)m * Un + j] = c[nt][i] + bp[j];
        }
    }
}

// ---------------- sampled logits: outputs @ Ws^T + svec, hit mask -----------
__global__ void __launch_bounds__(256) slog_kernel(const int* __restrict__ labels)
{
    __shared__ float AS[64][33];
    __shared__ float BS[32][65];

    const int tid = threadIdx.x;
    const int warp = tid >> 5, lane = tid & 31;
    const int g = lane >> 2, tig = lane & 3;
    const int rbase = (warp >> 1) * 16;
    const int cbase = (warp & 1) * 32;
    const int m0 = blockIdx.x * 64, jb = blockIdx.y * 64;

    float c[4][4];
    #pragma unroll
    for (int nt = 0; nt < 4; nt++)
        #pragma unroll
        for (int i = 0; i < 4; i++) c[nt][i] = 0.f;

    for (int t0 = 0; t0 < Un; t0 += 32) {
        #pragma unroll
        for (int r = 0; r < 2; r++) {
            int v = r * 256 + tid;
            int row = v >> 3, q = v & 7;
            const float* p = g_outputs + (size_t)(m0 + row) * Un + t0 + q * 4;
            float4 f = *(const float4*)p;
            AS[row][q*4+0] = __uint_as_float(to_tf32(f.x));
            AS[row][q*4+1] = __uint_as_float(to_tf32(f.y));
            AS[row][q*4+2] = __uint_as_float(to_tf32(f.z));
            AS[row][q*4+3] = __uint_as_float(to_tf32(f.w));
        }
        #pragma unroll
        for (int r = 0; r < 2; r++) {
            int v = r * 256 + tid;
            int j = v >> 3, q = v & 7;
            float4 f = *(const float4*)(g_Ws + (size_t)(jb + j) * Un + t0 + q * 4);
            BS[q*4+0][j] = __uint_as_float(to_tf32(f.x));
            BS[q*4+1][j] = __uint_as_float(to_tf32(f.y));
            BS[q*4+2][j] = __uint_as_float(to_tf32(f.z));
            BS[q*4+3][j] = __uint_as_float(to_tf32(f.w));
        }
        __syncthreads();

        #pragma unroll
        for (int k8 = 0; k8 < 32; k8 += 8) {
            unsigned a0 = __float_as_uint(AS[rbase + g    ][k8 + tig    ]);
            unsigned a1 = __float_as_uint(AS[rbase + g + 8][k8 + tig    ]);
            unsigned a2 = __float_as_uint(AS[rbase + g    ][k8 + tig + 4]);
            unsigned a3 = __float_as_uint(AS[rbase + g + 8][k8 + tig + 4]);
            #pragma unroll
            for (int nt = 0; nt < 4; nt++) {
                int j = cbase + nt * 8 + g;
                unsigned b0 = __float_as_uint(BS[k8 + tig    ][j]);
                unsigned b1 = __float_as_uint(BS[k8 + tig + 4][j]);
                mma8(c[nt], a0, a1, a2, a3, b0, b1);
            }
        }
        __syncthreads();
    }

    #pragma unroll
    for (int nt = 0; nt < 4; nt++) {
        #pragma unroll
        for (int i = 0; i < 4; i++) {
            int m = m0 + rbase + g + ((i >= 2) ? 8 : 0);
            int j = jb + cbase + nt * 8 + tig * 2 + (i & 1);
            float v = c[nt][i] + g_svec[j];
            if (labels[m] == g_sid[j]) v -= 1e9f;
            g_slog[(size_t)m * Sn + j] = v;
        }
    }
}

// ---------------- true logits: warp per row ---------------------------------
__global__ void __launch_bounds__(256) tlog_kernel(
    const int* __restrict__ labels, const float* __restrict__ sw,
    const float* __restrict__ sb, const float* __restrict__ tcnt)
{
    int warp = threadIdx.x >> 5, lane = threadIdx.x & 31;
    int n = blockIdx.x * 8 + warp;
    int lab = labels[n];
    const float4* o = (const float4*)(g_outputs + (size_t)n * Un);
    const float4* w = (const float4*)(sw + (size_t)lab * Un);
    float acc = 0.f;
    #pragma unroll
    for (int q = 0; q < 4; q++) {
        float4 a = o[lane + q * 32];
        float4 b = w[lane + q * 32];
        acc += a.x * b.x + a.y * b.y + a.z * b.z + a.w * b.w;
    }
    #pragma unroll
    for (int s = 16; s; s >>= 1) acc += __shfl_xor_sync(0xffffffffu, acc, s);
    if (lane == 0) g_tlog[n] = acc + sb[lab] - logf(tcnt[n]);
}

// ---------------- loss: warp per row, online logsumexp ----------------------
__global__ void __launch_bounds__(256) loss_kernel(float* __restrict__ out)
{
    __shared__ float red[8];
    int warp = threadIdx.x >> 5, lane = threadIdx.x & 31;
    int n = blockIdx.x * 8 + warp;

    float mL = -INFINITY, sL = 0.f;
    const float* row = g_slog + (size_t)n * Sn;
    for (int j = lane; j < Sn; j += 32) {
        float v = row[j];
        if (v > mL) { sL = sL * __expf(mL - v) + 1.f; mL = v; }
        else          sL += __expf(v - mL);
    }
    #pragma unroll
    for (int s = 16; s; s >>= 1) {
        float m2 = __shfl_xor_sync(0xffffffffu, mL, s);
        float s2 = __shfl_xor_sync(0xffffffffu, sL, s);
        float M = fmaxf(mL, m2);
        sL = sL * __expf(mL - M) + s2 * __expf(m2 - M);
        mL = M;
    }
    float z0 = g_tlog[n];
    float M = fmaxf(mL, z0);
    float S = sL * __expf(mL - M) + __expf(z0 - M);
    float loss = (M + logf(S)) - z0;

    if (lane == 0) red[warp] = loss;
    __syncthreads();
    if (threadIdx.x == 0) {
        float t = 0.f;
        #pragma unroll
        for (int i = 0; i < 8; i++) t += red[i];
        atomicAdd(out, t * (1.0f / NROWS));
    }
}

// ---------------- launch ----------------------------------------------------
extern "C" void kernel_launch(void* const* d_in, const int* in_sizes, int n_in,
                              void* d_out, int out_size)
{
    (void)in_sizes; (void)n_in; (void)out_size;

    const int*   input   = (const int*)  d_in[0];
    const int*   targets = (const int*)  d_in[1];
    const int*   sampled = (const int*)  d_in[2];
    const float* tcnt    = (const float*)d_in[3];
    const float* scnt    = (const float*)d_in[4];
    const float* emb     = (const float*)d_in[5];
    const float* Wh0     = (const float*)d_in[6];
    const float* bh0     = (const float*)d_in[7];
    const float* Wt0     = (const float*)d_in[8];
    const float* bt0     = (const float*)d_in[9];
    const float* Wh      = (const float*)d_in[10];
    const float* bh      = (const float*)d_in[11];
    const float* Wt      = (const float*)d_in[12];
    const float* bt      = (const float*)d_in[13];
    const float* Wp      = (const float*)d_in[14];
    const float* bp      = (const float*)d_in[15];
    const float* sw      = (const float*)d_in[16];
    const float* sb      = (const float*)d_in[17];
    float* out = (float*)d_out;

    const size_t OFF1 = (size_t)1024 * 1536;
    const size_t OFF2 = OFF1 + (size_t)1024 * 1024;

    cudaFuncSetAttribute(scan_kernel,
                         cudaFuncAttributeMaxDynamicSharedMemorySize, SCAN_SMEM);

    init_kernel<<<256, 256>>>(sampled, scnt, sw, sb, out);

    wconv_kernel<<<dim3(48, 32), 256>>>(Wh0, 0, 0, 1536);
    wconv_kernel<<<dim3(48, 32), 256>>>(Wt0, 1, 0, 1536);
    wconv_kernel<<<dim3(32, 32), 256>>>(Wh,                   0, OFF1, 1024);
    wconv_kernel<<<dim3(32, 32), 256>>>(Wt,                   1, OFF1, 1024);
    wconv_kernel<<<dim3(32, 32), 256>>>(Wh + (size_t)Rn * Rn, 0, OFF2, 1024);
    wconv_kernel<<<dim3(32, 32), 256>>>(Wt + (size_t)Rn * Rn, 1, OFF2, 1024);

    xconv_kernel<<<NROWS, 128>>>(input, emb);

    scan_kernel<<<NCTA, 256, SCAN_SMEM>>>(bh0, bt0, bh, bt);

    proj_kernel<<<dim3(NROWS / 64, Un / 64), 256>>>(Wp, bp);
    slog_kernel<<<dim3(NROWS / 64, Sn / 64), 256>>>(targets);
    tlog_kernel<<<NROWS / 8, 256>>>(targets, sw, sb, tcnt);
    loss_kernel<<<NROWS / 8, 256>>>(out);
}

// round 12
// speedup vs baseline: 5.8576x; 1.0539x over previous
#include <cuda_runtime.h>
#include <cuda_bf16.h>
#include <math.h>

// Problem dims
#define Vn 8000
#define Bn 64
#define Tn 256
#define Rn 1024
#define Un 512
#define Sn 1024
#define NROWS (Bn * Tn)  // 16384

#define NCTA 128
#define CH_COLS 256
#define ROW_STR 264                      // elems; 528 B rows

// smem W section offsets (elems). col stride = K+8 elems.
#define L0H 0
#define L0T 12352
#define L1H 24704
#define L1T 32960
#define L2H 41216
#define L2T 49472

// smem byte layout
#define OFF_BUF0 115456
#define BUF_B    33792                   // 64*264*2
#define OFF_HRAW (OFF_BUF0 + 3 * BUF_B)  // 216832
#define OFF_TRAW (OFF_HRAW + 2304)       // 219136
#define OFF_BAR  (OFF_TRAW + 2304)       // 221440
#define SCAN_SMEM (OFF_BAR + 32)         // 221472

// ---------------- device scratch (static globals; no runtime allocation) ----
__device__ float g_states[Tn * Bn * Rn];   // [t][b][r] fp32 final states (for proj)
__device__ float g_outputs[NROWS * Un];
__device__ float g_slog[NROWS * Sn];
__device__ float g_tlog[NROWS];
__device__ float g_Ws[Sn * Un];
__device__ float g_svec[Sn];
__device__ int   g_sid[Sn];

// bf16 scan data
__device__ __nv_bfloat16 g_xb[NROWS * Un];                     // [t][b][u]
__device__ __nv_bfloat16 g_WbH[1024 * 1536 + 2 * 1024 * 1024]; // [j][k] x3 layers
__device__ __nv_bfloat16 g_WbT[1024 * 1536 + 2 * 1024 * 1024];
__device__ __nv_bfloat16 g_sB[2 * Bn * Rn];                    // ping-pong L2-out
__device__ __nv_bfloat16 g_tmpA_B[Bn * Rn];                    // L0 out
__device__ __nv_bfloat16 g_tmpB_B[Bn * Rn];                    // L1 out

// per-(phase,quarter) producer counters: monotonic within one launch
__device__ unsigned g_cnt[768 * 4];

// ---------------- helpers ---------------------------------------------------
__device__ __forceinline__ unsigned to_tf32(float x) {
    unsigned r;
    asm("cvt.rna.tf32.f32 %0, %1;" : "=r"(r) : "f"(x));
    return r;
}

__device__ __forceinline__ void mma8(float c[4],
                                     unsigned a0, unsigned a1, unsigned a2, unsigned a3,
                                     unsigned b0, unsigned b1) {
    asm volatile(
        "mma.sync.aligned.m16n8k8.row.col.f32.tf32.tf32.f32 "
        "{%0,%1,%2,%3},{%4,%5,%6,%7},{%8,%9},{%0,%1,%2,%3};"
        : "+f"(c[0]), "+f"(c[1]), "+f"(c[2]), "+f"(c[3])
        : "r"(a0), "r"(a1), "r"(a2), "r"(a3), "r"(b0), "r"(b1));
}

__device__ __forceinline__ void mma_bf16(float c[4],
                                         unsigned a0, unsigned a1, unsigned a2, unsigned a3,
                                         unsigned b0, unsigned b1) {
    asm volatile(
        "mma.sync.aligned.m16n8k16.row.col.f32.bf16.bf16.f32 "
        "{%0,%1,%2,%3},{%4,%5,%6,%7},{%8,%9},{%0,%1,%2,%3};"
        : "+f"(c[0]), "+f"(c[1]), "+f"(c[2]), "+f"(c[3])
        : "r"(a0), "r"(a1), "r"(a2), "r"(a3), "r"(b0), "r"(b1));
}

__device__ __forceinline__ void ldsm4(unsigned& a0, unsigned& a1,
                                      unsigned& a2, unsigned& a3, unsigned addr) {
    asm volatile("ldmatrix.sync.aligned.m8n8.x4.shared.b16 {%0,%1,%2,%3}, [%4];"
                 : "=r"(a0), "=r"(a1), "=r"(a2), "=r"(a3) : "r"(addr));
}

__device__ __forceinline__ void waitBar(unsigned barU, unsigned parity) {
    asm volatile(
        "{\n\t.reg .pred P;\n\t"
        "WB_%=:\n\t"
        "mbarrier.try_wait.parity.acquire.cta.shared::cta.b64 P, [%0], %1, 0x989680;\n\t"
        "@!P bra WB_%=;\n\t}"
        :: "r"(barU), "r"(parity) : "memory");
}

__device__ __forceinline__ void pollCnt(const unsigned* p) {
    unsigned v;
    for (;;) {
        asm volatile("ld.acquire.gpu.global.u32 %0, [%1];" : "=r"(v) : "l"(p));
        if (v >= 32u) break;
        __nanosleep(32);
    }
}

// issue one chunk into a slot: 64 rows x 512 B via TMA bulk; tid0 polls dep first
__device__ __forceinline__ void issueSlot(unsigned bufU, unsigned barU,
    const __nv_bfloat16* src, int strideElems, int waitIdx, int tid)
{
    if (tid < 64) {
        if (waitIdx >= 0) {
            if (tid == 0) pollCnt(&g_cnt[waitIdx]);
            asm volatile("bar.sync 1, 64;" ::: "memory");
        }
        asm volatile("mbarrier.arrive.expect_tx.shared.b64 _, [%0], %1;"
                     :: "r"(barU), "r"(512) : "memory");
        unsigned dst = bufU + (unsigned)tid * (ROW_STR * 2);
        asm volatile(
            "cp.async.bulk.shared::cluster.global.mbarrier::complete_tx::bytes "
            "[%0], [%1], %2, [%3];"
            :: "r"(dst), "l"(src + (size_t)tid * strideElems), "r"(512), "r"(barU)
            : "memory");
    }
}

// ---------------- init ------------------------------------------------------
__global__ void __launch_bounds__(256) init_kernel(
    const int* __restrict__ sampled, const float* __restrict__ scnt,
    const float* __restrict__ sw, const float* __restrict__ sb,
    float* __restrict__ out)
{
    int gt = blockIdx.x * blockDim.x + threadIdx.x;
    int stride = gridDim.x * blockDim.x;
    if (gt == 0) out[0] = 0.0f;
    unsigned* sb32 = (unsigned*)g_sB;   // both ping-pong slots as words
    for (int i = gt; i < Bn * Rn; i += stride) sb32[i] = 0u;
    for (int i = gt; i < 768 * 4; i += stride) g_cnt[i] = 0u;
    for (int j = gt; j < Sn; j += stride) {
        int id = sampled[j];
        g_sid[j] = id;
        g_svec[j] = sb[id] - logf(scnt[j]);
    }
    for (int i = gt; i < Sn * Un; i += stride)
        g_Ws[i] = sw[(size_t)sampled[i >> 9] * Un + (i & 511)];
}

// ---------------- weight transpose/convert: f32 [K][1024] -> bf16 [1024][K] -
__global__ void __launch_bounds__(256) wconv_kernel(
    const float* __restrict__ src, int which, size_t dstOff, int K)
{
    __shared__ float tile[32][33];
    __nv_bfloat16* dst = (which ? g_WbT : g_WbH) + dstOff;
    int k0 = blockIdx.x * 32, j0 = blockIdx.y * 32;
    int tx = threadIdx.x & 31, ty = threadIdx.x >> 5;
    for (int r = ty; r < 32; r += 8)
        tile[r][tx] = src[(size_t)(k0 + r) * 1024 + j0 + tx];
    __syncthreads();
    for (int r = ty; r < 32; r += 8)
        dst[(size_t)(j0 + r) * K + k0 + tx] = __float2bfloat16_rn(tile[tx][r]);
}

// ---------------- emb pre-gather --------------------------------------------
__global__ void __launch_bounds__(128) xconv_kernel(
    const int* __restrict__ inp, const float* __restrict__ emb)
{
    int idx = blockIdx.x;               // t*64 + b
    int b = idx & 63, t = idx >> 6;
    int tok = inp[b * Tn + t];
    const float4* s = (const float4*)(emb + (size_t)tok * Un);
    __nv_bfloat162* d2 = (__nv_bfloat162*)(g_xb + (size_t)idx * Un);
    int v = threadIdx.x;
    float4 f = s[v];
    __nv_bfloat162 p0, p1;
    p0.x = __float2bfloat16_rn(f.x); p0.y = __float2bfloat16_rn(f.y);
    p1.x = __float2bfloat16_rn(f.z); p1.y = __float2bfloat16_rn(f.w);
    d2[2 * v] = p0;
    d2[2 * v + 1] = p1;
}

// ---------------- one highway phase (dual GEMM + gate) ----------------------
template<int K, int NCH, int nEmb>
__device__ __forceinline__ void doPhase(
    int rot, int pIdx, int waitPhase,
    int offHElems, int offTElems,
    const __nv_bfloat16* __restrict__ aEmb,
    const __nv_bfloat16* __restrict__ aState,
    float biasH, float biasT,
    float& s0, float& s1,
    __nv_bfloat16* __restrict__ dstB,
    float* __restrict__ stF,           // nullable (layer 2 only)
    char* smem, unsigned smemU,
    unsigned& ph0, unsigned& ph1, unsigned& ph2,
    int jbase, int tid, int w, int lane)
{
    const int g = lane >> 2, tig = lane & 3;
    const int mat = w >> 2, rbase = (w & 3) * 16;
    const int strW = K + 8;

    const unsigned lmOff = (unsigned)(((rbase + (lane & 15)) * ROW_STR
                                       + ((lane >> 4) << 3)) * 2);

    float acc0[4] = {0.f, 0.f, 0.f, 0.f}, acc1[4] = {0.f, 0.f, 0.f, 0.f};
    const unsigned* bw = (const unsigned*)((const __nv_bfloat16*)smem
                          + (mat ? offTElems : offHElems) + g * strW);

    // chunk order: emb chunks first (no dep), state chunks rotated by group
    auto lcOf = [&](int c) {
        return (c < nEmb) ? c : nEmb + ((rot + (c - nEmb)) & 3);
    };
    auto issueC = [&](int c) {
        int lc = lcOf(c);
        const __nv_bfloat16* src; int stride; int wi;
        if (lc < nEmb) { src = aEmb + lc * CH_COLS; stride = Un; wi = -1; }
        else {
            int gi = lc - nEmb;
            src = aState + (gi << 8); stride = Rn;
            wi = (waitPhase >= 0) ? waitPhase * 4 + gi : -1;
        }
        int slot = c % 3;
        issueSlot(smemU + OFF_BUF0 + slot * BUF_B, smemU + OFF_BAR + slot * 8,
                  src, stride, wi, tid);
    };

    constexpr int nPre = (NCH < 3) ? NCH : 3;
    #pragma unroll
    for (int i = 0; i < nPre; i++) issueC(i);

    #pragma unroll
    for (int c = 0; c < NCH; c++) {
        const int slot = c % 3;
        unsigned barU = smemU + OFF_BAR + slot * 8;
        unsigned par = (slot == 0) ? ph0 : (slot == 1) ? ph1 : ph2;
        waitBar(barU, par);
        if (slot == 0) ph0 ^= 1u; else if (slot == 1) ph1 ^= 1u; else ph2 ^= 1u;

        int lc = lcOf(c);
        unsigned aAddr = smemU + OFF_BUF0 + slot * BUF_B + lmOff;
        const unsigned* br = bw + (lc << 7) + tig;
        #pragma unroll
        for (int s8 = 0; s8 < 16; s8++) {
            unsigned a0, a1, a2, a3;
            ldsm4(a0, a1, a2, a3, aAddr + s8 * 32);
            unsigned b0 = br[s8 * 8], b1 = br[s8 * 8 + 4];
            if (s8 & 1) mma_bf16(acc1, a0, a1, a2, a3, b0, b1);
            else        mma_bf16(acc0, a0, a1, a2, a3, b0, b1);
        }
        __syncthreads();                  // slot buffer free
        if (c + 3 < NCH) issueC(c + 3);
    }

    float* hraw = (float*)(smem + OFF_HRAW);
    float* traw = (float*)(smem + OFF_TRAW);
    float* raw = mat ? traw : hraw;
    int r0 = rbase + g;
    raw[r0 * 9 + 2 * tig]           = acc0[0] + acc1[0];
    raw[r0 * 9 + 2 * tig + 1]       = acc0[1] + acc1[1];
    raw[(r0 + 8) * 9 + 2 * tig]     = acc0[2] + acc1[2];
    raw[(r0 + 8) * 9 + 2 * tig + 1] = acc0[3] + acc1[3];
    __syncthreads();

    // epilogue: thread owns rows (tid>>3) and (tid>>3)+32 at col jbase+(tid&7)
    int jj = tid & 7, jcol = jbase + jj, b0r = tid >> 3;
    {
        float hp = hraw[b0r * 9 + jj] + biasH;
        float tp = traw[b0r * 9 + jj] + biasT;
        float tg = 1.0f / (1.0f + __expf(-tp));
        float o = (tanhf(hp) - s0) * tg + s0;
        s0 = o;
        dstB[b0r * Rn + jcol] = __float2bfloat16_rn(o);
        if (stF) stF[b0r * Rn + jcol] = o;
    }
    {
        int b1r = b0r + 32;
        float hp = hraw[b1r * 9 + jj] + biasH;
        float tp = traw[b1r * 9 + jj] + biasT;
        float tg = 1.0f / (1.0f + __expf(-tp));
        float o = (tanhf(hp) - s1) * tg + s1;
        s1 = o;
        dstB[b1r * Rn + jcol] = __float2bfloat16_rn(o);
        if (stF) stF[b1r * Rn + jcol] = o;
    }
    __syncthreads();
    if (tid == 0)
        asm volatile("red.release.gpu.global.add.u32 [%0], %1;"
                     :: "l"(&g_cnt[pIdx * 4 + (blockIdx.x >> 5)]), "r"(1u) : "memory");
}

// ---------------- persistent scan kernel ------------------------------------
__global__ void __launch_bounds__(256) scan_kernel(
    const float* __restrict__ bh0, const float* __restrict__ bt0,
    const float* __restrict__ bh, const float* __restrict__ bt)
{
    extern __shared__ char smem[];
    const unsigned smemU = (unsigned)__cvta_generic_to_shared(smem);
    const int tid = threadIdx.x, w = tid >> 5, lane = tid & 31;
    const int jbase = blockIdx.x * 8;
    const int rot = ((blockIdx.x >> 5) + 1) & 3;
    const size_t GOFF1 = (size_t)1024 * 1536;
    const size_t GOFF2 = GOFF1 + (size_t)1024 * 1024;

    // preload this CTA's weight slice into smem (once)
    {
        const int Ks[6] = {1536, 1536, 1024, 1024, 1024, 1024};
        const int so[6] = {L0H, L0T, L1H, L1T, L2H, L2T};
        const size_t go[6] = {0, 0, GOFF1, GOFF1, GOFF2, GOFF2};
        __nv_bfloat16* wsm = (__nv_bfloat16*)smem;
        for (int sec = 0; sec < 6; sec++) {
            const __nv_bfloat16* gsrc = ((sec & 1) ? g_WbT : g_WbH)
                                        + go[sec] + (size_t)jbase * Ks[sec];
            int kv = Ks[sec] >> 3;            // uint4 per col
            int nv = Ks[sec];                 // 8 cols * kv
            for (int i = tid; i < nv; i += 256) {
                int col = i / kv, vi = i - col * kv;
                *(uint4*)(wsm + so[sec] + col * (Ks[sec] + 8) + vi * 8) =
                    *(const uint4*)(gsrc + (size_t)col * Ks[sec] + vi * 8);
            }
        }
    }
    if (tid == 0) {
        asm volatile("mbarrier.init.shared.b64 [%0], 64;" :: "r"(smemU + OFF_BAR) : "memory");
        asm volatile("mbarrier.init.shared.b64 [%0], 64;" :: "r"(smemU + OFF_BAR + 8) : "memory");
        asm volatile("mbarrier.init.shared.b64 [%0], 64;" :: "r"(smemU + OFF_BAR + 16) : "memory");
    }
    __syncthreads();

    // per-thread biases (col fixed across phases)
    int jcol = jbase + (tid & 7);
    float b0H = __ldg(&bh0[jcol]), b0T = __ldg(&bt0[jcol]);
    float b1H = __ldg(&bh[jcol]),  b1T = __ldg(&bt[jcol]);
    float b2H = __ldg(&bh[Rn + jcol]), b2T = __ldg(&bt[Rn + jcol]);

    float s0 = 0.f, s1 = 0.f;          // recurrent state (own cell), fp32
    unsigned ph0 = 0u, ph1 = 0u, ph2 = 0u;

    for (int t = 0; t < Tn; t++) {
        const __nv_bfloat16* xbt = g_xb + (size_t)t * Bn * Un;
        const __nv_bfloat16* prevL2 = g_sB + (size_t)((t + 1) & 1) * Bn * Rn;
        int p = 3 * t;

        doPhase<1536, 6, 2>(rot, p, (t ? p - 1 : -1), L0H, L0T, xbt, prevL2,
                            b0H, b0T, s0, s1, g_tmpA_B, nullptr,
                            smem, smemU, ph0, ph1, ph2, jbase, tid, w, lane);
        doPhase<1024, 4, 0>(rot, p + 1, p, L1H, L1T, nullptr, g_tmpA_B,
                            b1H, b1T, s0, s1, g_tmpB_B, nullptr,
                            smem, smemU, ph0, ph1, ph2, jbase, tid, w, lane);
        doPhase<1024, 4, 0>(rot, p + 2, p + 1, L2H, L2T, nullptr, g_tmpB_B,
                            b2H, b2T, s0, s1, g_sB + (size_t)(t & 1) * Bn * Rn,
                            g_states + (size_t)t * Bn * Rn,
                            smem, smemU, ph0, ph1, ph2, jbase, tid, w, lane);
    }
}

// ---------------- projection: outputs[m][u] = states . Wp + bp --------------
__global__ void __launch_bounds__(256) proj_kernel(
    const float* __restrict__ Wp, const float* __restrict__ bp)
{
    __shared__ float AS[64][33];
    __shared__ float BS[32][65];

    const int tid = threadIdx.x;
    const int warp = tid >> 5, lane = tid & 31;
    const int g = lane >> 2, tig = lane & 3;
    const int rbase = (warp >> 1) * 16;
    const int cbase = (warp & 1) * 32;
    const int m0 = blockIdx.x * 64, jb = blockIdx.y * 64;

    float c[4][4];
    #pragma unroll
    for (int nt = 0; nt < 4; nt++)
        #pragma unroll
        for (int i = 0; i < 4; i++) c[nt][i] = 0.f;

    for (int t0 = 0; t0 < Rn; t0 += 32) {
        #pragma unroll
        for (int r = 0; r < 2; r++) {
            int v = r * 256 + tid;
            int row = v >> 3, q = v & 7;
            int m = m0 + row;
            const float* p = g_states + (size_t)(m & (Tn - 1)) * (Bn * Rn)
                                      + (size_t)(m >> 8) * Rn + t0 + q * 4;
            float4 f = *(const float4*)p;
            AS[row][q*4+0] = __uint_as_float(to_tf32(f.x));
            AS[row][q*4+1] = __uint_as_float(to_tf32(f.y));
            AS[row][q*4+2] = __uint_as_float(to_tf32(f.z));
            AS[row][q*4+3] = __uint_as_float(to_tf32(f.w));
        }
        #pragma unroll
        for (int r = 0; r < 2; r++) {
            int v = r * 256 + tid;
            int kk = v >> 4, jq = v & 15;
            float4 f = *(const float4*)(Wp + (size_t)(t0 + kk) * Un + jb + jq * 4);
            BS[kk][jq*4+0] = __uint_as_float(to_tf32(f.x));
            BS[kk][jq*4+1] = __uint_as_float(to_tf32(f.y));
            BS[kk][jq*4+2] = __uint_as_float(to_tf32(f.z));
            BS[kk][jq*4+3] = __uint_as_float(to_tf32(f.w));
        }
        __syncthreads();

        #pragma unroll
        for (int k8 = 0; k8 < 32; k8 += 8) {
            unsigned a0 = __float_as_uint(AS[rbase + g    ][k8 + tig    ]);
            unsigned a1 = __float_as_uint(AS[rbase + g + 8][k8 + tig    ]);
            unsigned a2 = __float_as_uint(AS[rbase + g    ][k8 + tig + 4]);
            unsigned a3 = __float_as_uint(AS[rbase + g + 8][k8 + tig + 4]);
            #pragma unroll
            for (int nt = 0; nt < 4; nt++) {
                int j = cbase + nt * 8 + g;
                unsigned b0 = __float_as_uint(BS[k8 + tig    ][j]);
                unsigned b1 = __float_as_uint(BS[k8 + tig + 4][j]);
                mma8(c[nt], a0, a1, a2, a3, b0, b1);
            }
        }
        __syncthreads();
    }

    #pragma unroll
    for (int nt = 0; nt < 4; nt++) {
        #pragma unroll
        for (int i = 0; i < 4; i++) {
            int m = m0 + rbase + g + ((i >= 2) ? 8 : 0);
            int j = jb + cbase + nt * 8 + tig * 2 + (i & 1);
            g_outputs[(size_t)m * Un + j] = c[nt][i] + bp[j];
        }
    }
}

// ---------------- sampled logits: outputs @ Ws^T + svec, hit mask -----------
__global__ void __launch_bounds__(256) slog_kernel(const int* __restrict__ labels)
{
    __shared__ float AS[64][33];
    __shared__ float BS[32][65];

    const int tid = threadIdx.x;
    const int warp = tid >> 5, lane = tid & 31;
    const int g = lane >> 2, tig = lane & 3;
    const int rbase = (warp >> 1) * 16;
    const int cbase = (warp & 1) * 32;
    const int m0 = blockIdx.x * 64, jb = blockIdx.y * 64;

    float c[4][4];
    #pragma unroll
    for (int nt = 0; nt < 4; nt++)
        #pragma unroll
        for (int i = 0; i < 4; i++) c[nt][i] = 0.f;

    for (int t0 = 0; t0 < Un; t0 += 32) {
        #pragma unroll
        for (int r = 0; r < 2; r++) {
            int v = r * 256 + tid;
            int row = v >> 3, q = v & 7;
            const float* p = g_outputs + (size_t)(m0 + row) * Un + t0 + q * 4;
            float4 f = *(const float4*)p;
            AS[row][q*4+0] = __uint_as_float(to_tf32(f.x));
            AS[row][q*4+1] = __uint_as_float(to_tf32(f.y));
            AS[row][q*4+2] = __uint_as_float(to_tf32(f.z));
            AS[row][q*4+3] = __uint_as_float(to_tf32(f.w));
        }
        #pragma unroll
        for (int r = 0; r < 2; r++) {
            int v = r * 256 + tid;
            int j = v >> 3, q = v & 7;
            float4 f = *(const float4*)(g_Ws + (size_t)(jb + j) * Un + t0 + q * 4);
            BS[q*4+0][j] = __uint_as_float(to_tf32(f.x));
            BS[q*4+1][j] = __uint_as_float(to_tf32(f.y));
            BS[q*4+2][j] = __uint_as_float(to_tf32(f.z));
            BS[q*4+3][j] = __uint_as_float(to_tf32(f.w));
        }
        __syncthreads();

        #pragma unroll
        for (int k8 = 0; k8 < 32; k8 += 8) {
            unsigned a0 = __float_as_uint(AS[rbase + g    ][k8 + tig    ]);
            unsigned a1 = __float_as_uint(AS[rbase + g + 8][k8 + tig    ]);
            unsigned a2 = __float_as_uint(AS[rbase + g    ][k8 + tig + 4]);
            unsigned a3 = __float_as_uint(AS[rbase + g + 8][k8 + tig + 4]);
            #pragma unroll
            for (int nt = 0; nt < 4; nt++) {
                int j = cbase + nt * 8 + g;
                unsigned b0 = __float_as_uint(BS[k8 + tig    ][j]);
                unsigned b1 = __float_as_uint(BS[k8 + tig + 4][j]);
                mma8(c[nt], a0, a1, a2, a3, b0, b1);
            }
        }
        __syncthreads();
    }

    #pragma unroll
    for (int nt = 0; nt < 4; nt++) {
        #pragma unroll
        for (int i = 0; i < 4; i++) {
            int m = m0 + rbase + g + ((i >= 2) ? 8 : 0);
            int j = jb + cbase + nt * 8 + tig * 2 + (i & 1);
            float v = c[nt][i] + g_svec[j];
            if (labels[m] == g_sid[j]) v -= 1e9f;
            g_slog[(size_t)m * Sn + j] = v;
        }
    }
}

// ---------------- true logits: warp per row ---------------------------------
__global__ void __launch_bounds__(256) tlog_kernel(
    const int* __restrict__ labels, const float* __restrict__ sw,
    const float* __restrict__ sb, const float* __restrict__ tcnt)
{
    int warp = threadIdx.x >> 5, lane = threadIdx.x & 31;
    int n = blockIdx.x * 8 + warp;
    int lab = labels[n];
    const float4* o = (const float4*)(g_outputs + (size_t)n * Un);
    const float4* w = (const float4*)(sw + (size_t)lab * Un);
    float acc = 0.f;
    #pragma unroll
    for (int q = 0; q < 4; q++) {
        float4 a = o[lane + q * 32];
        float4 b = w[lane + q * 32];
        acc += a.x * b.x + a.y * b.y + a.z * b.z + a.w * b.w;
    }
    #pragma unroll
    for (int s = 16; s; s >>= 1) acc += __shfl_xor_sync(0xffffffffu, acc, s);
    if (lane == 0) g_tlog[n] = acc + sb[lab] - logf(tcnt[n]);
}

// ---------------- loss: warp per row, online logsumexp ----------------------
__global__ void __launch_bounds__(256) loss_kernel(float* __restrict__ out)
{
    __shared__ float red[8];
    int warp = threadIdx.x >> 5, lane = threadIdx.x & 31;
    int n = blockIdx.x * 8 + warp;

    float mL = -INFINITY, sL = 0.f;
    const float* row = g_slog + (size_t)n * Sn;
    for (int j = lane; j < Sn; j += 32) {
        float v = row[j];
        if (v > mL) { sL = sL * __expf(mL - v) + 1.f; mL = v; }
        else          sL += __expf(v - mL);
    }
    #pragma unroll
    for (int s = 16; s; s >>= 1) {
        float m2 = __shfl_xor_sync(0xffffffffu, mL, s);
        float s2 = __shfl_xor_sync(0xffffffffu, sL, s);
        float M = fmaxf(mL, m2);
        sL = sL * __expf(mL - M) + s2 * __expf(m2 - M);
        mL = M;
    }
    float z0 = g_tlog[n];
    float M = fmaxf(mL, z0);
    float S = sL * __expf(mL - M) + __expf(z0 - M);
    float loss = (M + logf(S)) - z0;

    if (lane == 0) red[warp] = loss;
    __syncthreads();
    if (threadIdx.x == 0) {
        float t = 0.f;
        #pragma unroll
        for (int i = 0; i < 8; i++) t += red[i];
        atomicAdd(out, t * (1.0f / NROWS));
    }
}

// ---------------- launch ----------------------------------------------------
extern "C" void kernel_launch(void* const* d_in, const int* in_sizes, int n_in,
                              void* d_out, int out_size)
{
    (void)in_sizes; (void)n_in; (void)out_size;

    const int*   input   = (const int*)  d_in[0];
    const int*   targets = (const int*)  d_in[1];
    const int*   sampled = (const int*)  d_in[2];
    const float* tcnt    = (const float*)d_in[3];
    const float* scnt    = (const float*)d_in[4];
    const float* emb     = (const float*)d_in[5];
    const float* Wh0     = (const float*)d_in[6];
    const float* bh0     = (const float*)d_in[7];
    const float* Wt0     = (const float*)d_in[8];
    const float* bt0     = (const float*)d_in[9];
    const float* Wh      = (const float*)d_in[10];
    const float* bh      = (const float*)d_in[11];
    const float* Wt      = (const float*)d_in[12];
    const float* bt      = (const float*)d_in[13];
    const float* Wp      = (const float*)d_in[14];
    const float* bp      = (const float*)d_in[15];
    const float* sw      = (const float*)d_in[16];
    const float* sb      = (const float*)d_in[17];
    float* out = (float*)d_out;

    const size_t OFF1 = (size_t)1024 * 1536;
    const size_t OFF2 = OFF1 + (size_t)1024 * 1024;

    cudaFuncSetAttribute(scan_kernel,
                         cudaFuncAttributeMaxDynamicSharedMemorySize, SCAN_SMEM);

    init_kernel<<<256, 256>>>(sampled, scnt, sw, sb, out);

    wconv_kernel<<<dim3(48, 32), 256>>>(Wh0, 0, 0, 1536);
    wconv_kernel<<<dim3(48, 32), 256>>>(Wt0, 1, 0, 1536);
    wconv_kernel<<<dim3(32, 32), 256>>>(Wh,                   0, OFF1, 1024);
    wconv_kernel<<<dim3(32, 32), 256>>>(Wt,                   1, OFF1, 1024);
    wconv_kernel<<<dim3(32, 32), 256>>>(Wh + (size_t)Rn * Rn, 0, OFF2, 1024);
    wconv_kernel<<<dim3(32, 32), 256>>>(Wt + (size_t)Rn * Rn, 1, OFF2, 1024);

    xconv_kernel<<<NROWS, 128>>>(input, emb);

    scan_kernel<<<NCTA, 256, SCAN_SMEM>>>(bh0, bt0, bh, bt);

    proj_kernel<<<dim3(NROWS / 64, Un / 64), 256>>>(Wp, bp);
    slog_kernel<<<dim3(NROWS / 64, Sn / 64), 256>>>(targets);
    tlog_kernel<<<NROWS / 8, 256>>>(targets, sw, sb, tcnt);
    loss_kernel<<<NROWS / 8, 256>>>(out);
}